// round 9
// baseline (speedup 1.0000x reference)
#include <cuda_runtime.h>

// B=8, N=1024, D=256, H=512, M=256, O=256, 4H=2048

__device__ float g_xproj[8 * 1024 * 2048];
__device__ float g_h    [8 * 1024 * 512];
__device__ float g_t1   [8 * 1024 * 256];
__device__ float g_t2   [8 * 1024 * 256];
__device__ float g_t3   [8 * 1024 * 256];
__device__ float g_ax   [8 * 1024 * 256];
__device__ float g_av   [8 * 1024 * 256];
__device__ float g_scores[8 * 1024 * 1024];
__device__ float g_sagg [8 * 1024 * 512];
__device__ float g_agg  [8 * 1024 * 256];
__device__ int   g_hasnb[8 * 1024];
__device__ unsigned g_ctr[1024];

__device__ __forceinline__ unsigned ld_acq(const unsigned* p) {
    unsigned v;
    asm volatile("ld.acquire.gpu.global.u32 %0, [%1];" : "=r"(v) : "l"(p) : "memory");
    return v;
}
__device__ __forceinline__ void red_rel_add(unsigned* p, unsigned v) {
    asm volatile("red.add.release.gpu.global.u32 [%0], %1;" :: "l"(p), "r"(v) : "memory");
}
__device__ __forceinline__ unsigned long long pk2(float lo, float hi) {
    unsigned long long r;
    asm("mov.b64 %0, {%1, %2};" : "=l"(r) : "f"(lo), "f"(hi));
    return r;
}
__device__ __forceinline__ void fma2(unsigned long long& d, unsigned long long a, unsigned long long b) {
    asm("fma.rn.f32x2 %0, %1, %2, %0;" : "+l"(d) : "l"(a), "l"(b));
}
__device__ __forceinline__ float unpk_sum(unsigned long long v) {
    float x, y;
    asm("mov.b64 {%0, %1}, %2;" : "=f"(x), "=f"(y) : "l"(v));
    return x + y;
}
__device__ __forceinline__ float sigf(float x) {
    return __fdividef(1.f, 1.f + __expf(-x));
}
__device__ __forceinline__ float tanhfast(float x) {
    return __fdividef(2.f, 1.f + __expf(-2.f * x)) - 1.f;
}
__device__ __forceinline__ void barhalf(int half) {
    asm volatile("bar.sync %0, 128;" :: "r"(1 + half) : "memory");
}
__device__ __forceinline__ unsigned smem_u32(const void* p) {
    unsigned a;
    asm("{ .reg .u64 t; cvta.to.shared.u64 t, %1; cvt.u32.u64 %0, t; }" : "=r"(a) : "l"(p));
    return a;
}
__device__ __forceinline__ void cp16(unsigned saddr, const void* gptr) {
    asm volatile("cp.async.cg.shared.global [%0], [%1], 16;" :: "r"(saddr), "l"(gptr));
}
__device__ __forceinline__ void cp_commit_wait() {
    asm volatile("cp.async.commit_group;\ncp.async.wait_group 0;" ::: "memory");
}

__global__ void reset_kernel() {
    g_ctr[threadIdx.x] = 0u;
}

// ---------- persistent LSTM: 128 CTAs x 256 thr; CTA owns 4 j-cols (16 gate rows) ----------
// Two fully independent batch-halves per CTA: warps 0-3 (batches 0-3), warps 4-7 (batches 4-7).
// warp w: gate rw = w&3, batch group bw = w>>2 (== half). Gate warps: 0 and 4.
// Counter threshold 256 (each half arrives independently).
__global__ __launch_bounds__(256, 1) void lstm_kernel(const float* __restrict__ Whh)
{
    __shared__ __align__(16) float hs[8 * 512];
    __shared__ float gsum[16][8];

    const int tid  = threadIdx.x;
    const int w    = tid >> 5;
    const int lane = tid & 31;
    const int j0   = blockIdx.x * 4;
    const int rw   = w & 3;    // gate
    const int bw   = w >> 2;   // batch group == half
    const int half = tid >> 7;
    const int htid = tid & 127;
    const bool gatewarp = (lane < 16) && (rw == 0);

    // weights: 4 rows (gate rw, j-locals 0..3) x 16 k, packed f32x2
    unsigned long long wq[4][8];
    #pragma unroll
    for (int r = 0; r < 4; r++) {
        const size_t grow = (size_t)(rw * 512 + j0 + r) * 512;
        #pragma unroll
        for (int i = 0; i < 4; i++) {
            float4 a = *(const float4*)&Whh[grow + 4 * lane + 128 * i];
            wq[r][2 * i]     = pk2(a.x, a.y);
            wq[r][2 * i + 1] = pk2(a.z, a.w);
        }
    }

    float c_st = 0.f;
    const int gb  = 4 * half + (lane >> 2);  // gate-warp batch
    const int gjl = lane & 3;                // gate-warp local j

    // precompute staging addresses (4 x 16B per thread, within own half)
    unsigned sa[4];
    const float* ga[4];
    #pragma unroll
    for (int q = 0; q < 4; q++) {
        int idx16 = htid + 128 * q;                 // float4 index within half (512 total)
        int bl = idx16 >> 7, k4 = idx16 & 127;
        int b = 4 * half + bl;
        sa[q] = smem_u32(&hs[(b * 512) + 4 * k4]);
        ga[q] = &g_h[((size_t)(b << 10)) * 512 + 4 * k4];  // + (t-1)*512 at use
    }

    for (int t = 0; t < 1024; ++t) {
        // prefetch x-projection gate inputs (independent of h[t-1])
        float xq0 = 0.f, xq1 = 0.f, xq2 = 0.f, xq3 = 0.f;
        if (gatewarp) {
            size_t base = ((size_t)(gb << 10) + t) * 2048 + j0 + gjl;
            xq0 = g_xproj[base];
            xq1 = g_xproj[base + 512];
            xq2 = g_xproj[base + 1024];
            xq3 = g_xproj[base + 1536];
        }

        // one poller per half waits for both halves of all 128 CTAs
        if (t > 0 && htid == 0) {
            while (ld_acq(&g_ctr[t - 1]) < 256u) { }
        }
        barhalf(half);

        // stage own half's 4 batches of h[t-1] (8KB) via cp.async
        if (t == 0) {
            #pragma unroll
            for (int q = 0; q < 4; q++) {
                int idx16 = htid + 128 * q;
                int bl = idx16 >> 7, k4 = idx16 & 127;
                *(float4*)&hs[(4 * half + bl) * 512 + 4 * k4] =
                    make_float4(0.f, 0.f, 0.f, 0.f);
            }
        } else {
            const size_t toff = (size_t)(t - 1) * 512;
            #pragma unroll
            for (int q = 0; q < 4; q++)
                cp16(sa[q], ga[q] + toff);
            cp_commit_wait();
        }
        barhalf(half);

        // matvec: 4 rows x 4 batches per warp
        unsigned long long acc[16];
        #pragma unroll
        for (int j = 0; j < 16; j++) acc[j] = 0ull;
        #pragma unroll
        for (int i = 0; i < 4; i++) {
            const int kb = 4 * lane + 128 * i;
            #pragma unroll
            for (int bb = 0; bb < 4; bb++) {
                ulonglong2 hv = *(const ulonglong2*)&hs[(4 * bw + bb) * 512 + kb];
                #pragma unroll
                for (int r = 0; r < 4; r++) {
                    fma2(acc[r * 4 + bb], wq[r][2 * i],     hv.x);
                    fma2(acc[r * 4 + bb], wq[r][2 * i + 1], hv.y);
                }
            }
        }

        float v[16];
        #pragma unroll
        for (int j = 0; j < 16; j++) v[j] = unpk_sum(acc[j]);

        // folded butterfly: bits 16,8,4,2 fold 16 values -> 1, bit 1 finishes k-reduce
        float t16[16];
        #pragma unroll
        for (int j = 0; j < 16; j++) t16[j] = __shfl_xor_sync(0xffffffffu, v[j], 16);
        const int s16 = (lane & 16) ? 8 : 0;
        float w8[8];
        #pragma unroll
        for (int j = 0; j < 8; j++) w8[j] = v[s16 + j] + t16[s16 + j];
        float t8[8];
        #pragma unroll
        for (int j = 0; j < 8; j++) t8[j] = __shfl_xor_sync(0xffffffffu, w8[j], 8);
        const int s8 = (lane & 8) ? 4 : 0;
        float w4[4];
        #pragma unroll
        for (int j = 0; j < 4; j++) w4[j] = w8[s8 + j] + t8[s8 + j];
        float t4[4];
        #pragma unroll
        for (int j = 0; j < 4; j++) t4[j] = __shfl_xor_sync(0xffffffffu, w4[j], 4);
        const int s4 = (lane & 4) ? 2 : 0;
        float w2[2];
        #pragma unroll
        for (int j = 0; j < 2; j++) w2[j] = w4[s4 + j] + t4[s4 + j];
        float t2a = __shfl_xor_sync(0xffffffffu, w2[0], 2);
        float t2b = __shfl_xor_sync(0xffffffffu, w2[1], 2);
        float w1 = (lane & 2) ? (w2[1] + t2b) : (w2[0] + t2a);
        float z = w1 + __shfl_xor_sync(0xffffffffu, w1, 1);

        // lane -> (r, bb): idx = 8*b4 + 4*b3 + 2*b2 + 1*b1
        const int idx = ((lane >> 4) & 1) * 8 + ((lane >> 3) & 1) * 4 +
                        ((lane >> 2) & 1) * 2 + ((lane >> 1) & 1);
        if (!(lane & 1))
            gsum[4 * rw + (idx >> 2)][4 * bw + (idx & 3)] = z;
        barhalf(half);

        // per-half gate warp (warp 0 / warp 4): 16 lanes = 4 batches x 4 j
        if (rw == 0) {
            if (lane < 16) {
                float gi = gsum[0  + gjl][gb] + xq0;
                float gf = gsum[4  + gjl][gb] + xq1;
                float gg = gsum[8  + gjl][gb] + xq2;
                float go = gsum[12 + gjl][gb] + xq3;
                float si = sigf(gi);
                float sf = sigf(gf);
                float so = sigf(go);
                float tg = tanhfast(gg);
                c_st = sf * c_st + si * tg;
                float hN = so * tanhfast(c_st);
                g_h[((size_t)(gb << 10) + t) * 512 + j0 + gjl] = hN;
            }
            __syncwarp();
            if (lane == 0) red_rel_add(&g_ctr[t], 1u);
        }
    }
}

// ---------- generic tiled fp32 GEMM ----------
// TB==0: B is [N,K] row-major (NT). TB==1: B is [K,N] (NN). M,N %128==0, K%8==0.
// DUAL: blockIdx.z==1 switches to (dA,dB,dBias,dC,dldb) with RELU2 epilogue.
template<int TB, bool RELU, bool ACC, bool DUAL, bool RELU2>
__global__ __launch_bounds__(256) void gemm_kernel(
    const float* __restrict__ A, int lda, long long strideA,
    const float* __restrict__ B, int ldb, long long strideB,
    float* __restrict__ C, int ldc, long long strideC,
    int M, int N, int K,
    const float* __restrict__ bias, const float* __restrict__ bias2,
    const int* __restrict__ rowmask,
    const float* __restrict__ dA, const float* __restrict__ dB,
    const float* __restrict__ dBias, float* __restrict__ dC, int dldb)
{
    __shared__ __align__(16) float As[2][8][128];
    __shared__ __align__(16) float Bs[2][8][128];

    const int tid = threadIdx.x;
    const int m0 = blockIdx.y * 128;
    const int n0 = blockIdx.x * 128;
    bool relu = RELU;
    if (DUAL) {
        if (blockIdx.z == 1) { A = dA; B = dB; bias = dBias; C = dC; ldb = dldb; relu = RELU2; }
    } else {
        A += (long long)blockIdx.z * strideA;
        B += (long long)blockIdx.z * strideB;
        C += (long long)blockIdx.z * strideC;
    }

    const int ar   = tid >> 1;
    const int aseg = (tid & 1) * 4;
    const int bk   = tid >> 5;
    const int bn   = (tid & 31) * 4;
    const int nk   = K >> 3;

    {
        float4 a4 = *(const float4*)(A + (size_t)(m0 + ar) * lda + aseg);
        As[0][aseg + 0][ar] = a4.x; As[0][aseg + 1][ar] = a4.y;
        As[0][aseg + 2][ar] = a4.z; As[0][aseg + 3][ar] = a4.w;
        if (TB == 0) {
            float4 b4 = *(const float4*)(B + (size_t)(n0 + ar) * ldb + aseg);
            Bs[0][aseg + 0][ar] = b4.x; Bs[0][aseg + 1][ar] = b4.y;
            Bs[0][aseg + 2][ar] = b4.z; Bs[0][aseg + 3][ar] = b4.w;
        } else {
            *(float4*)&Bs[0][bk][bn] = *(const float4*)(B + (size_t)bk * ldb + n0 + bn);
        }
    }
    __syncthreads();

    float acc[8][8];
    #pragma unroll
    for (int i = 0; i < 8; i++)
        #pragma unroll
        for (int j = 0; j < 8; j++) acc[i][j] = 0.f;

    const int tm = (tid >> 4) << 3;
    const int tn = (tid & 15) << 3;

    for (int kt = 0; kt < nk; ++kt) {
        const int cur = kt & 1, nxt = cur ^ 1;
        float4 na, nb;
        if (kt + 1 < nk) {
            const int k0 = (kt + 1) << 3;
            na = *(const float4*)(A + (size_t)(m0 + ar) * lda + k0 + aseg);
            if (TB == 0)
                nb = *(const float4*)(B + (size_t)(n0 + ar) * ldb + k0 + aseg);
            else
                nb = *(const float4*)(B + (size_t)(k0 + bk) * ldb + n0 + bn);
        }
        #pragma unroll
        for (int kk = 0; kk < 8; ++kk) {
            float4 aa0 = *(const float4*)&As[cur][kk][tm];
            float4 aa1 = *(const float4*)&As[cur][kk][tm + 4];
            float4 bb0 = *(const float4*)&Bs[cur][kk][tn];
            float4 bb1 = *(const float4*)&Bs[cur][kk][tn + 4];
            float av_[8] = {aa0.x, aa0.y, aa0.z, aa0.w, aa1.x, aa1.y, aa1.z, aa1.w};
            float bv_[8] = {bb0.x, bb0.y, bb0.z, bb0.w, bb1.x, bb1.y, bb1.z, bb1.w};
            #pragma unroll
            for (int i = 0; i < 8; i++)
                #pragma unroll
                for (int j = 0; j < 8; j++)
                    acc[i][j] = fmaf(av_[i], bv_[j], acc[i][j]);
        }
        if (kt + 1 < nk) {
            As[nxt][aseg + 0][ar] = na.x; As[nxt][aseg + 1][ar] = na.y;
            As[nxt][aseg + 2][ar] = na.z; As[nxt][aseg + 3][ar] = na.w;
            if (TB == 0) {
                Bs[nxt][aseg + 0][ar] = nb.x; Bs[nxt][aseg + 1][ar] = nb.y;
                Bs[nxt][aseg + 2][ar] = nb.z; Bs[nxt][aseg + 3][ar] = nb.w;
            } else {
                *(float4*)&Bs[nxt][bk][bn] = nb;
            }
        }
        __syncthreads();
    }

    float bvv[8];
    #pragma unroll
    for (int j = 0; j < 8; j++) {
        float b = bias ? bias[n0 + tn + j] : 0.f;
        if (bias2) b += bias2[n0 + tn + j];
        bvv[j] = b;
    }
    #pragma unroll
    for (int i = 0; i < 8; i++) {
        const int row = m0 + tm + i;
        float keep = 1.f;
        if (rowmask) keep = rowmask[row] ? 1.f : 0.f;
        float out[8];
        #pragma unroll
        for (int j = 0; j < 8; j++) {
            float v = acc[i][j] + bvv[j];
            if (relu) v = fmaxf(v, 0.f);
            out[j] = v * keep;
        }
        float* Cp = C + (size_t)row * ldc + n0 + tn;
        if (ACC) {
            float4 o0 = *(const float4*)Cp;
            float4 o1 = *(const float4*)(Cp + 4);
            out[0] += o0.x; out[1] += o0.y; out[2] += o0.z; out[3] += o0.w;
            out[4] += o1.x; out[5] += o1.y; out[6] += o1.z; out[7] += o1.w;
        }
        *(float4*)Cp       = make_float4(out[0], out[1], out[2], out[3]);
        *(float4*)(Cp + 4) = make_float4(out[4], out[5], out[6], out[7]);
    }
}

// ---------- masked softmax per row (in place) + has-neighbor flag ----------
__global__ __launch_bounds__(256) void softmax_kernel(
    float* __restrict__ S, const int* __restrict__ adj, int* __restrict__ hasnb)
{
    __shared__ float sred[32];
    const int r = blockIdx.x;
    const int i = r & 1023;
    const int tid = threadIdx.x;
    float* Sr = S + (size_t)r * 1024;
    const int* Ar = adj + (size_t)r * 1024;

    float v[4]; int ok[4];
    float mx = -3.0e38f;
    #pragma unroll
    for (int q = 0; q < 4; q++) {
        int j = tid + 256 * q;
        ok[q] = (Ar[j] > 0) && (j != i);
        v[q] = Sr[j];
        if (ok[q]) mx = fmaxf(mx, v[q]);
    }
    #pragma unroll
    for (int off = 16; off > 0; off >>= 1)
        mx = fmaxf(mx, __shfl_xor_sync(0xffffffffu, mx, off));
    if ((tid & 31) == 0) sred[tid >> 5] = mx;
    __syncthreads();
    if (tid < 32) {
        float m2 = (tid < 8) ? sred[tid] : -3.0e38f;
        #pragma unroll
        for (int off = 4; off > 0; off >>= 1)
            m2 = fmaxf(m2, __shfl_xor_sync(0xffffffffu, m2, off));
        if (tid == 0) sred[0] = m2;
    }
    __syncthreads();
    const float rowmax = sred[0];
    const bool any = rowmax > -1.0e37f;

    float e[4];
    float s = 0.f;
    #pragma unroll
    for (int q = 0; q < 4; q++) {
        e[q] = ok[q] ? __expf(v[q] - rowmax) : 0.f;
        s += e[q];
    }
    #pragma unroll
    for (int off = 16; off > 0; off >>= 1)
        s += __shfl_xor_sync(0xffffffffu, s, off);
    __syncthreads();
    if ((tid & 31) == 0) sred[tid >> 5] = s;
    __syncthreads();
    if (tid < 32) {
        float s2 = (tid < 8) ? sred[tid] : 0.f;
        #pragma unroll
        for (int off = 4; off > 0; off >>= 1)
            s2 += __shfl_xor_sync(0xffffffffu, s2, off);
        if (tid == 0) sred[0] = s2;
    }
    __syncthreads();
    const float inv = any ? (1.f / sred[0]) : 0.f;
    #pragma unroll
    for (int q = 0; q < 4; q++)
        Sr[tid + 256 * q] = e[q] * inv;
    if (tid == 0) hasnb[r] = any ? 1 : 0;
}

extern "C" void kernel_launch(void* const* d_in, const int* in_sizes, int n_in,
                              void* d_out, int out_size)
{
    const float* feats  = (const float*)d_in[0];
    const int*   adj    = (const int*)  d_in[1];
    const float* W_ih   = (const float*)d_in[2];
    const float* W_hh   = (const float*)d_in[3];
    const float* b_ih   = (const float*)d_in[4];
    const float* b_hh   = (const float*)d_in[5];
    const float* gx_W1  = (const float*)d_in[6];
    const float* gx_b1  = (const float*)d_in[7];
    const float* gx_W2  = (const float*)d_in[8];
    const float* gx_b2  = (const float*)d_in[9];
    const float* gz_W1  = (const float*)d_in[10];
    const float* gz_b1  = (const float*)d_in[11];
    const float* gz_W2  = (const float*)d_in[12];
    const float* gz_b2  = (const float*)d_in[13];
    const float* gv_W1  = (const float*)d_in[14];
    const float* gv_b1  = (const float*)d_in[15];
    const float* gv_W2  = (const float*)d_in[16];
    const float* gv_b2  = (const float*)d_in[17];
    const float* gn_W1  = (const float*)d_in[18];
    const float* gn_b1  = (const float*)d_in[19];
    const float* gn_W2  = (const float*)d_in[20];
    const float* gn_b2  = (const float*)d_in[21];
    const float* out_W  = (const float*)d_in[22];
    const float* out_b  = (const float*)d_in[23];
    float* out = (float*)d_out;

    float *xproj, *h, *t1, *t2, *t3, *ax, *av, *scores, *sagg, *agg;
    int* hasnb;
    cudaGetSymbolAddress((void**)&xproj,  g_xproj);
    cudaGetSymbolAddress((void**)&h,      g_h);
    cudaGetSymbolAddress((void**)&t1,     g_t1);
    cudaGetSymbolAddress((void**)&t2,     g_t2);
    cudaGetSymbolAddress((void**)&t3,     g_t3);
    cudaGetSymbolAddress((void**)&ax,     g_ax);
    cudaGetSymbolAddress((void**)&av,     g_av);
    cudaGetSymbolAddress((void**)&scores, g_scores);
    cudaGetSymbolAddress((void**)&sagg,   g_sagg);
    cudaGetSymbolAddress((void**)&agg,    g_agg);
    cudaGetSymbolAddress((void**)&hasnb,  g_hasnb);

    reset_kernel<<<1, 1024>>>();

    // x_proj = feats @ W_ih^T + (b_ih + b_hh) : [8192,2048], K=256
    gemm_kernel<0, false, false, false, false><<<dim3(16, 64, 1), 256>>>(
        feats, 256, 0, W_ih, 256, 0, xproj, 2048, 0,
        8192, 2048, 256, b_ih, b_hh, nullptr,
        nullptr, nullptr, nullptr, nullptr, 0);

    lstm_kernel<<<128, 256>>>(W_hh);

    // ax/av MLP layer 1 (paired): h@gx_W1^T->t1 ; h@gv_W1^T->t3
    gemm_kernel<0, true , false, true, true><<<dim3(2, 64, 2), 256>>>(
        h, 512, 0, gx_W1, 512, 0, t1, 256, 0, 8192, 256, 512, gx_b1, nullptr, nullptr,
        h, gv_W1, gv_b1, t3, 512);
    // ax/av MLP layer 2 (paired): t1@gx_W2^T->ax ; t3@gv_W2^T->av
    gemm_kernel<0, false, false, true, false><<<dim3(2, 64, 2), 256>>>(
        t1, 256, 0, gx_W2, 256, 0, ax, 256, 0, 8192, 256, 256, gx_b2, nullptr, nullptr,
        t3, gv_W2, gv_b2, av, 256);

    // scores[b] = ax[b] @ av[b]^T
    gemm_kernel<0, false, false, false, false><<<dim3(8, 8, 8), 256>>>(
        ax, 256, 1024LL * 256, av, 256, 1024LL * 256,
        scores, 1024, 1024LL * 1024, 1024, 1024, 256, nullptr, nullptr, nullptr,
        nullptr, nullptr, nullptr, nullptr, 0);

    softmax_kernel<<<8192, 256>>>(scores, adj, hasnb);

    // sagg[b] = w[b] @ h[b]
    gemm_kernel<1, false, false, false, false><<<dim3(4, 8, 8), 256>>>(
        scores, 1024, 1024LL * 1024, h, 512, 1024LL * 512,
        sagg, 512, 1024LL * 512, 1024, 512, 1024, nullptr, nullptr, nullptr,
        nullptr, nullptr, nullptr, nullptr, 0);

    // paired: out_part = h @ out_W[:, :512]^T + out_b  ;  t1 = relu(sagg@gz_W1^T + gz_b1)
    gemm_kernel<0, false, false, true, true><<<dim3(2, 64, 2), 256>>>(
        h, 512, 0, out_W, 768, 0, out, 256, 0, 8192, 256, 512, out_b, nullptr, nullptr,
        sagg, gz_W1, gz_b1, t1, 512);

    // agg = MLP_gn(MLP_gz(...)) with isolated-node zeroing
    gemm_kernel<0, false, false, false, false><<<dim3(2, 64, 1), 256>>>(
        t1, 256, 0, gz_W2, 256, 0, t2, 256, 0, 8192, 256, 256, gz_b2, nullptr, nullptr,
        nullptr, nullptr, nullptr, nullptr, 0);
    gemm_kernel<0, true , false, false, false><<<dim3(2, 64, 1), 256>>>(
        t2, 256, 0, gn_W1, 256, 0, t1, 256, 0, 8192, 256, 256, gn_b1, nullptr, nullptr,
        nullptr, nullptr, nullptr, nullptr, 0);
    gemm_kernel<0, false, false, false, false><<<dim3(2, 64, 1), 256>>>(
        t1, 256, 0, gn_W2, 256, 0, agg, 256, 0, 8192, 256, 256, gn_b2, nullptr, hasnb,
        nullptr, nullptr, nullptr, nullptr, 0);

    // out += agg @ out_W[:, 512:]^T
    gemm_kernel<0, false, true , false, false><<<dim3(2, 64, 1), 256>>>(
        agg, 256, 0, out_W + 512, 768, 0, out, 256, 0, 8192, 256, 256, nullptr, nullptr, nullptr,
        nullptr, nullptr, nullptr, nullptr, 0);
}

// round 11
// speedup vs baseline: 1.1417x; 1.1417x over previous
#include <cuda_runtime.h>
#include <cuda_bf16.h>

// B=8, N=1024, D=256, H=512, M=256, O=256, 4H=2048

__device__ float g_xproj[8 * 1024 * 2048];
__device__ float g_h    [8 * 1024 * 512];
__device__ float g_hT   [8 * 512 * 1024];
__device__ float g_t1   [8 * 1024 * 256];
__device__ float g_t2   [8 * 1024 * 256];
__device__ float g_t3   [8 * 1024 * 256];
__device__ float g_ax   [8 * 1024 * 256];
__device__ float g_av   [8 * 1024 * 256];
__device__ float g_scores[8 * 1024 * 1024];
__device__ float g_sagg [8 * 1024 * 512];
__device__ float g_agg  [8 * 1024 * 256];
__device__ float g_bsum [2048];
__device__ int   g_hasnb[8 * 1024];
__device__ unsigned g_ctr[1024];

// ---------------- helpers ----------------
__device__ __forceinline__ unsigned ld_acq(const unsigned* p) {
    unsigned v;
    asm volatile("ld.acquire.gpu.global.u32 %0, [%1];" : "=r"(v) : "l"(p) : "memory");
    return v;
}
__device__ __forceinline__ void red_rel_add(unsigned* p, unsigned v) {
    asm volatile("red.add.release.gpu.global.u32 [%0], %1;" :: "l"(p), "r"(v) : "memory");
}
__device__ __forceinline__ unsigned long long pk2(float lo, float hi) {
    unsigned long long r;
    asm("mov.b64 %0, {%1, %2};" : "=l"(r) : "f"(lo), "f"(hi));
    return r;
}
__device__ __forceinline__ void fma2(unsigned long long& d, unsigned long long a, unsigned long long b) {
    asm("fma.rn.f32x2 %0, %1, %2, %0;" : "+l"(d) : "l"(a), "l"(b));
}
__device__ __forceinline__ float unpk_sum(unsigned long long v) {
    float x, y;
    asm("mov.b64 {%0, %1}, %2;" : "=f"(x), "=f"(y) : "l"(v));
    return x + y;
}
__device__ __forceinline__ float sigf(float x) {
    return __fdividef(1.f, 1.f + __expf(-x));
}
__device__ __forceinline__ float tanhfast(float x) {
    return __fdividef(2.f, 1.f + __expf(-2.f * x)) - 1.f;
}
__device__ __forceinline__ void barhalf(int half) {
    asm volatile("bar.sync %0, 128;" :: "r"(1 + half) : "memory");
}
__device__ __forceinline__ unsigned smem_u32(const void* p) {
    unsigned a;
    asm("{ .reg .u64 t; cvta.to.shared.u64 t, %1; cvt.u32.u64 %0, t; }" : "=r"(a) : "l"(p));
    return a;
}
__device__ __forceinline__ void ldsm4(unsigned* r, unsigned addr) {
    asm volatile("ldmatrix.sync.aligned.m8n8.x4.shared.b16 {%0,%1,%2,%3}, [%4];"
                 : "=r"(r[0]), "=r"(r[1]), "=r"(r[2]), "=r"(r[3]) : "r"(addr));
}
__device__ __forceinline__ void mma16816(float* c, const unsigned* a, const unsigned* b) {
    asm volatile(
        "mma.sync.aligned.m16n8k16.row.col.f32.bf16.bf16.f32 "
        "{%0,%1,%2,%3}, {%4,%5,%6,%7}, {%8,%9}, {%0,%1,%2,%3};"
        : "+f"(c[0]), "+f"(c[1]), "+f"(c[2]), "+f"(c[3])
        : "r"(a[0]), "r"(a[1]), "r"(a[2]), "r"(a[3]), "r"(b[0]), "r"(b[1]));
}

__global__ void reset_kernel(const float* __restrict__ b_ih, const float* __restrict__ b_hh) {
    int t = threadIdx.x;
    g_ctr[t] = 0u;
    g_bsum[t] = b_ih[t] + b_hh[t];
    g_bsum[t + 1024] = b_ih[t + 1024] + b_hh[t + 1024];
}

// ---------- persistent LSTM (R8-best version): 128 CTAs x 256 thr ----------
__global__ __launch_bounds__(256, 1) void lstm_kernel(const float* __restrict__ Whh)
{
    __shared__ __align__(16) float hs[8 * 512];
    __shared__ float gsum[16][8];

    const int tid  = threadIdx.x;
    const int w    = tid >> 5;
    const int lane = tid & 31;
    const int j0   = blockIdx.x * 4;
    const int rw   = w & 3;
    const int bw   = w >> 2;
    const int half = tid >> 7;
    const int htid = tid & 127;

    unsigned long long wq[4][8];
    #pragma unroll
    for (int r = 0; r < 4; r++) {
        const size_t grow = (size_t)(rw * 512 + j0 + r) * 512;
        #pragma unroll
        for (int i = 0; i < 4; i++) {
            float4 a = *(const float4*)&Whh[grow + 4 * lane + 128 * i];
            wq[r][2 * i]     = pk2(a.x, a.y);
            wq[r][2 * i + 1] = pk2(a.z, a.w);
        }
    }

    float c_st = 0.f;
    const int ub  = lane >> 2;
    const int ujl = lane & 3;

    for (int t = 0; t < 1024; ++t) {
        float xq0 = 0.f, xq1 = 0.f, xq2 = 0.f, xq3 = 0.f;
        if (tid < 32) {
            size_t base = ((size_t)(ub << 10) + t) * 2048 + j0 + ujl;
            xq0 = g_xproj[base];
            xq1 = g_xproj[base + 512];
            xq2 = g_xproj[base + 1024];
            xq3 = g_xproj[base + 1536];
        }

        if (t > 0 && htid == 0) {
            while (ld_acq(&g_ctr[t - 1]) < 128u) { }
        }
        barhalf(half);

        if (t == 0) {
            #pragma unroll
            for (int q = 0; q < 4; q++)
                *(float4*)&hs[(half * 512 + htid + 128 * q) * 4] =
                    make_float4(0.f, 0.f, 0.f, 0.f);
        } else {
            #pragma unroll
            for (int q = 0; q < 4; q++) {
                int flat = (half * 512 + htid + 128 * q) * 4;
                int b = flat >> 9, k = flat & 511;
                *(float4*)&hs[flat] =
                    *(const float4*)&g_h[((size_t)(b << 10) + (t - 1)) * 512 + k];
            }
        }
        barhalf(half);

        unsigned long long acc[16];
        #pragma unroll
        for (int j = 0; j < 16; j++) acc[j] = 0ull;
        #pragma unroll
        for (int i = 0; i < 4; i++) {
            const int kb = 4 * lane + 128 * i;
            #pragma unroll
            for (int bb = 0; bb < 4; bb++) {
                ulonglong2 hv = *(const ulonglong2*)&hs[(4 * bw + bb) * 512 + kb];
                #pragma unroll
                for (int r = 0; r < 4; r++) {
                    fma2(acc[r * 4 + bb], wq[r][2 * i],     hv.x);
                    fma2(acc[r * 4 + bb], wq[r][2 * i + 1], hv.y);
                }
            }
        }

        float v[16];
        #pragma unroll
        for (int j = 0; j < 16; j++) v[j] = unpk_sum(acc[j]);

        float t16[16];
        #pragma unroll
        for (int j = 0; j < 16; j++) t16[j] = __shfl_xor_sync(0xffffffffu, v[j], 16);
        const int s16 = (lane & 16) ? 8 : 0;
        float w8[8];
        #pragma unroll
        for (int j = 0; j < 8; j++) w8[j] = v[s16 + j] + t16[s16 + j];
        float t8[8];
        #pragma unroll
        for (int j = 0; j < 8; j++) t8[j] = __shfl_xor_sync(0xffffffffu, w8[j], 8);
        const int s8 = (lane & 8) ? 4 : 0;
        float w4[4];
        #pragma unroll
        for (int j = 0; j < 4; j++) w4[j] = w8[s8 + j] + t8[s8 + j];
        float t4[4];
        #pragma unroll
        for (int j = 0; j < 4; j++) t4[j] = __shfl_xor_sync(0xffffffffu, w4[j], 4);
        const int s4 = (lane & 4) ? 2 : 0;
        float w2[2];
        #pragma unroll
        for (int j = 0; j < 2; j++) w2[j] = w4[s4 + j] + t4[s4 + j];
        float t2a = __shfl_xor_sync(0xffffffffu, w2[0], 2);
        float t2b = __shfl_xor_sync(0xffffffffu, w2[1], 2);
        float w1 = (lane & 2) ? (w2[1] + t2b) : (w2[0] + t2a);
        float z = w1 + __shfl_xor_sync(0xffffffffu, w1, 1);

        const int idx = ((lane >> 4) & 1) * 8 + ((lane >> 3) & 1) * 4 +
                        ((lane >> 2) & 1) * 2 + ((lane >> 1) & 1);
        if (!(lane & 1))
            gsum[4 * rw + (idx >> 2)][4 * bw + (idx & 3)] = z;
        __syncthreads();

        if (tid < 32) {
            float gi = gsum[0  + ujl][ub] + xq0;
            float gf = gsum[4  + ujl][ub] + xq1;
            float gg = gsum[8  + ujl][ub] + xq2;
            float go = gsum[12 + ujl][ub] + xq3;
            float si = sigf(gi);
            float sf = sigf(gf);
            float so = sigf(go);
            float tg = tanhfast(gg);
            c_st = sf * c_st + si * tg;
            float hN = so * tanhfast(c_st);
            g_h[((size_t)(ub << 10) + t) * 512 + j0 + ujl] = hN;
            __syncwarp();
            if (lane == 0) red_rel_add(&g_ctr[t], 1u);
        }
    }
}

// ---------- bf16x3 tensor-core GEMM via mma.sync (baseline ISA, works at compute_103) ----------
// C[M,N] = A[M,K] @ B[N,K]^T (+bias) (ReLU) (ACC) (rowmask). CTA 128x128, K-chunks of 32.
// 8 warps: warp_m = wid&3 (32 rows), warp_n = wid>>2 (64 cols). bf16 hi/lo planes, 3 MMAs/frag.
template<bool RELU, bool ACC, bool MASK>
__global__ __launch_bounds__(256, 1) void mma_gemm(
    const float* __restrict__ A, int lda, long long sA,
    const float* __restrict__ B, int ldb, long long sB,
    float* __restrict__ C, int ldc, long long sC,
    int K, const float* __restrict__ bias, const int* __restrict__ rowmask)
{
    __shared__ __align__(16) __nv_bfloat16 Ah[128][40], Al[128][40];
    __shared__ __align__(16) __nv_bfloat16 Bh[128][40], Bl[128][40];

    const int tid = threadIdx.x, wid = tid >> 5, lane = tid & 31;
    const int m0 = blockIdx.y * 128, n0 = blockIdx.x * 128;
    const int wm = wid & 3, wn = wid >> 2;
    A += (long long)blockIdx.z * sA;
    B += (long long)blockIdx.z * sB;
    C += (long long)blockIdx.z * sC;

    const int srow = tid >> 1;           // 0..127
    const int kseg = (tid & 1) * 16;     // 0 or 16
    const float* Ap = A + (size_t)(m0 + srow) * lda + kseg;
    const float* Bp = B + (size_t)(n0 + srow) * ldb + kseg;

    float c[2][8][4];
    #pragma unroll
    for (int i = 0; i < 2; i++)
        #pragma unroll
        for (int j = 0; j < 8; j++)
            #pragma unroll
            for (int q = 0; q < 4; q++) c[i][j][q] = 0.f;

    // ldmatrix base addresses (row = base + lane&15, col = k0 + 8*(lane>>4))
    const int lr = lane & 15, lc = (lane >> 4) << 3;

    const int nkt = K >> 5;
    float4 pa[4], pb[4];
    #pragma unroll
    for (int i = 0; i < 4; i++) {
        pa[i] = *(const float4*)(Ap + i * 4);
        pb[i] = *(const float4*)(Bp + i * 4);
    }

    for (int kt = 0; kt < nkt; ++kt) {
        // convert + store staged chunk
        #pragma unroll
        for (int i = 0; i < 4; i++) {
            float4 a = pa[i], b = pb[i];
            int kk = kseg + 4 * i;
            __nv_bfloat162 h01 = __floats2bfloat162_rn(a.x, a.y);
            __nv_bfloat162 h23 = __floats2bfloat162_rn(a.z, a.w);
            *(__nv_bfloat162*)&Ah[srow][kk]     = h01;
            *(__nv_bfloat162*)&Ah[srow][kk + 2] = h23;
            *(__nv_bfloat162*)&Al[srow][kk]     = __floats2bfloat162_rn(
                a.x - __bfloat162float(h01.x), a.y - __bfloat162float(h01.y));
            *(__nv_bfloat162*)&Al[srow][kk + 2] = __floats2bfloat162_rn(
                a.z - __bfloat162float(h23.x), a.w - __bfloat162float(h23.y));
            __nv_bfloat162 g01 = __floats2bfloat162_rn(b.x, b.y);
            __nv_bfloat162 g23 = __floats2bfloat162_rn(b.z, b.w);
            *(__nv_bfloat162*)&Bh[srow][kk]     = g01;
            *(__nv_bfloat162*)&Bh[srow][kk + 2] = g23;
            *(__nv_bfloat162*)&Bl[srow][kk]     = __floats2bfloat162_rn(
                b.x - __bfloat162float(g01.x), b.y - __bfloat162float(g01.y));
            *(__nv_bfloat162*)&Bl[srow][kk + 2] = __floats2bfloat162_rn(
                b.z - __bfloat162float(g23.x), b.w - __bfloat162float(g23.y));
        }
        __syncthreads();

        if (kt + 1 < nkt) {
            const int ko = (kt + 1) << 5;
            #pragma unroll
            for (int i = 0; i < 4; i++) {
                pa[i] = *(const float4*)(Ap + ko + i * 4);
                pb[i] = *(const float4*)(Bp + ko + i * 4);
            }
        }

        #pragma unroll
        for (int k16 = 0; k16 < 2; ++k16) {
            const int k0 = k16 * 16 + lc;
            unsigned ah[2][4], al[2][4], bh[8][2], bl[8][2];
            #pragma unroll
            for (int mf = 0; mf < 2; mf++) {
                ldsm4(ah[mf], smem_u32(&Ah[wm * 32 + mf * 16 + lr][k0]));
                ldsm4(al[mf], smem_u32(&Al[wm * 32 + mf * 16 + lr][k0]));
            }
            #pragma unroll
            for (int ng = 0; ng < 4; ng++) {
                unsigned th[4], tl[4];
                ldsm4(th, smem_u32(&Bh[wn * 64 + ng * 16 + lr][k0]));
                ldsm4(tl, smem_u32(&Bl[wn * 64 + ng * 16 + lr][k0]));
                bh[2 * ng][0] = th[0]; bh[2 * ng][1] = th[2];
                bh[2 * ng + 1][0] = th[1]; bh[2 * ng + 1][1] = th[3];
                bl[2 * ng][0] = tl[0]; bl[2 * ng][1] = tl[2];
                bl[2 * ng + 1][0] = tl[1]; bl[2 * ng + 1][1] = tl[3];
            }
            #pragma unroll
            for (int mf = 0; mf < 2; mf++)
                #pragma unroll
                for (int nf = 0; nf < 8; nf++) {
                    mma16816(c[mf][nf], ah[mf], bh[nf]);
                    mma16816(c[mf][nf], ah[mf], bl[nf]);
                    mma16816(c[mf][nf], al[mf], bh[nf]);
                }
        }
        __syncthreads();
    }

    // epilogue
    #pragma unroll
    for (int mf = 0; mf < 2; mf++) {
        const int row0 = m0 + wm * 32 + mf * 16 + (lane >> 2);
        const int row1 = row0 + 8;
        float keep0 = 1.f, keep1 = 1.f;
        if (MASK) {
            keep0 = rowmask[row0] ? 1.f : 0.f;
            keep1 = rowmask[row1] ? 1.f : 0.f;
        }
        #pragma unroll
        for (int nf = 0; nf < 8; nf++) {
            const int col = n0 + wn * 64 + nf * 8 + 2 * (lane & 3);
            float b0 = 0.f, b1 = 0.f;
            if (bias) { b0 = bias[col]; b1 = bias[col + 1]; }
            float o00 = c[mf][nf][0] + b0, o01 = c[mf][nf][1] + b1;
            float o10 = c[mf][nf][2] + b0, o11 = c[mf][nf][3] + b1;
            if (RELU) {
                o00 = fmaxf(o00, 0.f); o01 = fmaxf(o01, 0.f);
                o10 = fmaxf(o10, 0.f); o11 = fmaxf(o11, 0.f);
            }
            o00 *= keep0; o01 *= keep0; o10 *= keep1; o11 *= keep1;
            float* p0 = C + (size_t)row0 * ldc + col;
            float* p1 = C + (size_t)row1 * ldc + col;
            if (ACC) {
                float2 u0 = *(float2*)p0, u1 = *(float2*)p1;
                o00 += u0.x; o01 += u0.y; o10 += u1.x; o11 += u1.y;
            }
            *(float2*)p0 = make_float2(o00, o01);
            *(float2*)p1 = make_float2(o10, o11);
        }
    }
}

// ---------- transpose h[b][1024][512] -> hT[b][512][1024] ----------
__global__ __launch_bounds__(256) void transpose_kernel(
    const float* __restrict__ src, float* __restrict__ dst)
{
    __shared__ float tile[32][33];
    const int b = blockIdx.z;
    const int i0 = blockIdx.y * 32, j0 = blockIdx.x * 32;
    const int tx = threadIdx.x & 31, ty = threadIdx.x >> 5;
    #pragma unroll
    for (int rr = 0; rr < 32; rr += 8)
        tile[ty + rr][tx] = src[(size_t)b * 524288 + (size_t)(i0 + ty + rr) * 512 + j0 + tx];
    __syncthreads();
    #pragma unroll
    for (int rr = 0; rr < 32; rr += 8)
        dst[(size_t)b * 524288 + (size_t)(j0 + ty + rr) * 1024 + i0 + tx] = tile[tx][ty + rr];
}

// ---------- masked softmax per row (in place) + has-neighbor flag ----------
__global__ __launch_bounds__(256) void softmax_kernel(
    float* __restrict__ S, const int* __restrict__ adj, int* __restrict__ hasnb)
{
    __shared__ float sred[32];
    const int r = blockIdx.x;
    const int i = r & 1023;
    const int tid = threadIdx.x;
    float* Sr = S + (size_t)r * 1024;
    const int* Ar = adj + (size_t)r * 1024;

    float v[4]; int ok[4];
    float mx = -3.0e38f;
    #pragma unroll
    for (int q = 0; q < 4; q++) {
        int j = tid + 256 * q;
        ok[q] = (Ar[j] > 0) && (j != i);
        v[q] = Sr[j];
        if (ok[q]) mx = fmaxf(mx, v[q]);
    }
    #pragma unroll
    for (int off = 16; off > 0; off >>= 1)
        mx = fmaxf(mx, __shfl_xor_sync(0xffffffffu, mx, off));
    if ((tid & 31) == 0) sred[tid >> 5] = mx;
    __syncthreads();
    if (tid < 32) {
        float m2 = (tid < 8) ? sred[tid] : -3.0e38f;
        #pragma unroll
        for (int off = 4; off > 0; off >>= 1)
            m2 = fmaxf(m2, __shfl_xor_sync(0xffffffffu, m2, off));
        if (tid == 0) sred[0] = m2;
    }
    __syncthreads();
    const float rowmax = sred[0];
    const bool any = rowmax > -1.0e37f;

    float e[4];
    float s = 0.f;
    #pragma unroll
    for (int q = 0; q < 4; q++) {
        e[q] = ok[q] ? __expf(v[q] - rowmax) : 0.f;
        s += e[q];
    }
    #pragma unroll
    for (int off = 16; off > 0; off >>= 1)
        s += __shfl_xor_sync(0xffffffffu, s, off);
    __syncthreads();
    if ((tid & 31) == 0) sred[tid >> 5] = s;
    __syncthreads();
    if (tid < 32) {
        float s2 = (tid < 8) ? sred[tid] : 0.f;
        #pragma unroll
        for (int off = 4; off > 0; off >>= 1)
            s2 += __shfl_xor_sync(0xffffffffu, s2, off);
        if (tid == 0) sred[0] = s2;
    }
    __syncthreads();
    const float inv = any ? (1.f / sred[0]) : 0.f;
    #pragma unroll
    for (int q = 0; q < 4; q++)
        Sr[tid + 256 * q] = e[q] * inv;
    if (tid == 0) hasnb[r] = any ? 1 : 0;
}

extern "C" void kernel_launch(void* const* d_in, const int* in_sizes, int n_in,
                              void* d_out, int out_size)
{
    const float* feats  = (const float*)d_in[0];
    const int*   adj    = (const int*)  d_in[1];
    const float* W_ih   = (const float*)d_in[2];
    const float* W_hh   = (const float*)d_in[3];
    const float* b_ih   = (const float*)d_in[4];
    const float* b_hh   = (const float*)d_in[5];
    const float* gx_W1  = (const float*)d_in[6];
    const float* gx_b1  = (const float*)d_in[7];
    const float* gx_W2  = (const float*)d_in[8];
    const float* gx_b2  = (const float*)d_in[9];
    const float* gz_W1  = (const float*)d_in[10];
    const float* gz_b1  = (const float*)d_in[11];
    const float* gz_W2  = (const float*)d_in[12];
    const float* gz_b2  = (const float*)d_in[13];
    const float* gv_W1  = (const float*)d_in[14];
    const float* gv_b1  = (const float*)d_in[15];
    const float* gv_W2  = (const float*)d_in[16];
    const float* gv_b2  = (const float*)d_in[17];
    const float* gn_W1  = (const float*)d_in[18];
    const float* gn_b1  = (const float*)d_in[19];
    const float* gn_W2  = (const float*)d_in[20];
    const float* gn_b2  = (const float*)d_in[21];
    const float* out_W  = (const float*)d_in[22];
    const float* out_b  = (const float*)d_in[23];
    float* out = (float*)d_out;

    float *xproj, *h, *hT, *t1, *t2, *t3, *ax, *av, *scores, *sagg, *agg, *bsum;
    int* hasnb;
    cudaGetSymbolAddress((void**)&xproj,  g_xproj);
    cudaGetSymbolAddress((void**)&h,      g_h);
    cudaGetSymbolAddress((void**)&hT,     g_hT);
    cudaGetSymbolAddress((void**)&t1,     g_t1);
    cudaGetSymbolAddress((void**)&t2,     g_t2);
    cudaGetSymbolAddress((void**)&t3,     g_t3);
    cudaGetSymbolAddress((void**)&ax,     g_ax);
    cudaGetSymbolAddress((void**)&av,     g_av);
    cudaGetSymbolAddress((void**)&scores, g_scores);
    cudaGetSymbolAddress((void**)&sagg,   g_sagg);
    cudaGetSymbolAddress((void**)&agg,    g_agg);
    cudaGetSymbolAddress((void**)&bsum,   g_bsum);
    cudaGetSymbolAddress((void**)&hasnb,  g_hasnb);

    reset_kernel<<<1, 1024>>>(b_ih, b_hh);

    // x_proj = feats @ W_ih^T + (b_ih + b_hh) : [8192,2048], K=256
    mma_gemm<false, false, false><<<dim3(16, 64, 1), 256>>>(
        feats, 256, 0, W_ih, 256, 0, xproj, 2048, 0, 256, bsum, nullptr);

    lstm_kernel<<<128, 256>>>(W_hh);

    // ax = MLP_gx(h), av = MLP_gv(h)
    mma_gemm<true , false, false><<<dim3(2, 64, 1), 256>>>(
        h, 512, 0, gx_W1, 512, 0, t1, 256, 0, 512, gx_b1, nullptr);
    mma_gemm<true , false, false><<<dim3(2, 64, 1), 256>>>(
        h, 512, 0, gv_W1, 512, 0, t3, 256, 0, 512, gv_b1, nullptr);
    mma_gemm<false, false, false><<<dim3(2, 64, 1), 256>>>(
        t1, 256, 0, gx_W2, 256, 0, ax, 256, 0, 256, gx_b2, nullptr);
    mma_gemm<false, false, false><<<dim3(2, 64, 1), 256>>>(
        t3, 256, 0, gv_W2, 256, 0, av, 256, 0, 256, gv_b2, nullptr);

    // scores[b] = ax[b] @ av[b]^T
    mma_gemm<false, false, false><<<dim3(8, 8, 8), 256>>>(
        ax, 256, 262144LL, av, 256, 262144LL, scores, 1024, 1048576LL, 256, nullptr, nullptr);

    softmax_kernel<<<8192, 256>>>(scores, adj, hasnb);

    // hT = transpose(h); sagg[b] = w[b] @ h[b]  (NT via hT)
    transpose_kernel<<<dim3(16, 32, 8), 256>>>(h, hT);
    mma_gemm<false, false, false><<<dim3(4, 8, 8), 256>>>(
        scores, 1024, 1048576LL, hT, 1024, 524288LL, sagg, 512, 524288LL, 1024, nullptr, nullptr);

    // agg = MLP_gn(MLP_gz(sagg)), isolated nodes zeroed at the last layer
    mma_gemm<true , false, false><<<dim3(2, 64, 1), 256>>>(
        sagg, 512, 0, gz_W1, 512, 0, t1, 256, 0, 512, gz_b1, nullptr);
    mma_gemm<false, false, false><<<dim3(2, 64, 1), 256>>>(
        t1, 256, 0, gz_W2, 256, 0, t2, 256, 0, 256, gz_b2, nullptr);
    mma_gemm<true , false, false><<<dim3(2, 64, 1), 256>>>(
        t2, 256, 0, gn_W1, 256, 0, t1, 256, 0, 256, gn_b1, nullptr);
    mma_gemm<false, false, true ><<<dim3(2, 64, 1), 256>>>(
        t1, 256, 0, gn_W2, 256, 0, agg, 256, 0, 256, gn_b2, hasnb);

    // out = h @ out_W[:, :512]^T + out_b ; out += agg @ out_W[:, 512:]^T
    mma_gemm<false, false, false><<<dim3(2, 64, 1), 256>>>(
        h, 512, 0, out_W, 768, 0, out, 256, 0, 512, out_b, nullptr);
    mma_gemm<false, true , false><<<dim3(2, 64, 1), 256>>>(
        agg, 256, 0, out_W + 512, 768, 0, out, 256, 0, 256, nullptr, nullptr);
}

// round 13
// speedup vs baseline: 1.1943x; 1.0461x over previous
#include <cuda_runtime.h>
#include <cuda_bf16.h>

// B=8, N=1024, D=256, H=512, M=256, O=256, 4H=2048

__device__ float g_xproj[8 * 1024 * 2048];
__device__ float g_h    [8 * 1024 * 512];
__device__ float g_hT   [8 * 512 * 1024];
__device__ float g_t1   [8 * 1024 * 256];
__device__ float g_t2   [8 * 1024 * 256];
__device__ float g_t3   [8 * 1024 * 256];
__device__ float g_ax   [8 * 1024 * 256];
__device__ float g_av   [8 * 1024 * 256];
__device__ float g_scores[8 * 1024 * 1024];
__device__ float g_sagg [8 * 1024 * 512];
__device__ float g_agg  [8 * 1024 * 256];
__device__ float g_bsum [2048];
__device__ int   g_hasnb[8 * 1024];
__device__ unsigned g_ctr[4096];   // [group][t]

// ---------------- helpers ----------------
__device__ __forceinline__ unsigned ld_acq(const unsigned* p) {
    unsigned v;
    asm volatile("ld.acquire.gpu.global.u32 %0, [%1];" : "=r"(v) : "l"(p) : "memory");
    return v;
}
__device__ __forceinline__ void red_rel_add(unsigned* p, unsigned v) {
    asm volatile("red.add.release.gpu.global.u32 [%0], %1;" :: "l"(p), "r"(v) : "memory");
}
__device__ __forceinline__ unsigned long long pk2(float lo, float hi) {
    unsigned long long r;
    asm("mov.b64 %0, {%1, %2};" : "=l"(r) : "f"(lo), "f"(hi));
    return r;
}
__device__ __forceinline__ void fma2(unsigned long long& d, unsigned long long a, unsigned long long b) {
    asm("fma.rn.f32x2 %0, %1, %2, %0;" : "+l"(d) : "l"(a), "l"(b));
}
__device__ __forceinline__ float unpk_sum(unsigned long long v) {
    float x, y;
    asm("mov.b64 {%0, %1}, %2;" : "=f"(x), "=f"(y) : "l"(v));
    return x + y;
}
__device__ __forceinline__ float sigf(float x) {
    return __fdividef(1.f, 1.f + __expf(-x));
}
__device__ __forceinline__ float tanhfast(float x) {
    return __fdividef(2.f, 1.f + __expf(-2.f * x)) - 1.f;
}
__device__ __forceinline__ unsigned smem_u32(const void* p) {
    unsigned a;
    asm("{ .reg .u64 t; cvta.to.shared.u64 t, %1; cvt.u32.u64 %0, t; }" : "=r"(a) : "l"(p));
    return a;
}
__device__ __forceinline__ void ldsm4(unsigned* r, unsigned addr) {
    asm volatile("ldmatrix.sync.aligned.m8n8.x4.shared.b16 {%0,%1,%2,%3}, [%4];"
                 : "=r"(r[0]), "=r"(r[1]), "=r"(r[2]), "=r"(r[3]) : "r"(addr));
}
__device__ __forceinline__ void mma16816(float* c, const unsigned* a, const unsigned* b) {
    asm volatile(
        "mma.sync.aligned.m16n8k16.row.col.f32.bf16.bf16.f32 "
        "{%0,%1,%2,%3}, {%4,%5,%6,%7}, {%8,%9}, {%0,%1,%2,%3};"
        : "+f"(c[0]), "+f"(c[1]), "+f"(c[2]), "+f"(c[3])
        : "r"(a[0]), "r"(a[1]), "r"(a[2]), "r"(a[3]), "r"(b[0]), "r"(b[1]));
}

__global__ void reset_kernel(const float* __restrict__ b_ih, const float* __restrict__ b_hh) {
    int t = threadIdx.x;
    #pragma unroll
    for (int i = 0; i < 4; i++) g_ctr[t + 1024 * i] = 0u;
    g_bsum[t] = b_ih[t] + b_hh[t];
    g_bsum[t + 1024] = b_ih[t + 1024] + b_hh[t + 1024];
}

// ---------- persistent LSTM: 4 independent batch-pair chains x 32 CTAs ----------
// group = blockIdx>>5 owns batches {2g, 2g+1}. CTA-in-group cg owns j in [16cg, 16cg+16),
// all 4 gates (64 gate rows). Warp w owns jl in {2w, 2w+1} x 4 gates (8 rows).
// Weights register-stationary: 128 fp32 (as 64 f32x2) per thread.
__global__ __launch_bounds__(256, 1) void lstm_kernel(const float* __restrict__ Whh)
{
    __shared__ __align__(16) float hs[2 * 512];
    __shared__ float gsum[4][16][2];

    const int tid   = threadIdx.x;
    const int w     = tid >> 5;
    const int lane  = tid & 31;
    const int group = blockIdx.x >> 5;
    const int cg    = blockIdx.x & 31;
    const int j0    = cg * 16;
    const int b0    = group * 2;
    unsigned* ctr   = &g_ctr[group * 1024];

    // weights: 8 rows (gate = r&3, jl = 2w + (r>>2)) x 16 k (k = 4*lane + 128*i)
    unsigned long long wq[8][8];
    #pragma unroll
    for (int r = 0; r < 8; r++) {
        const int gt = r & 3;
        const int jl = 2 * w + (r >> 2);
        const size_t grow = (size_t)(gt * 512 + j0 + jl) * 512;
        #pragma unroll
        for (int i = 0; i < 4; i++) {
            float4 a = *(const float4*)&Whh[grow + 4 * lane + 128 * i];
            wq[r][2 * i]     = pk2(a.x, a.y);
            wq[r][2 * i + 1] = pk2(a.z, a.w);
        }
    }

    float c_st = 0.f;
    const int gjl = lane >> 1;    // gate-warp local j
    const int gbb = lane & 1;     // gate-warp batch-in-pair
    const int gB  = b0 + gbb;     // gate-warp global batch

    for (int t = 0; t < 1024; ++t) {
        // prefetch x-projection gate inputs (independent of h[t-1])
        float xq0 = 0.f, xq1 = 0.f, xq2 = 0.f, xq3 = 0.f;
        if (w == 0) {
            size_t base = ((size_t)(gB << 10) + t) * 2048 + j0 + gjl;
            xq0 = g_xproj[base];
            xq1 = g_xproj[base + 512];
            xq2 = g_xproj[base + 1024];
            xq3 = g_xproj[base + 1536];
        }

        // single-lane wait for this group's 32 CTAs
        if (t > 0 && tid == 0) {
            while (ld_acq(&ctr[t - 1]) < 32u) { }
        }
        __syncthreads();

        // stage this pair's h[t-1] (4KB): thread -> one float4
        if (t == 0) {
            *(float4*)&hs[4 * tid] = make_float4(0.f, 0.f, 0.f, 0.f);
        } else {
            int b = tid >> 7, k4 = tid & 127;
            *(float4*)&hs[4 * tid] =
                *(const float4*)&g_h[((size_t)((b0 + b) << 10) + (t - 1)) * 512 + 4 * k4];
        }
        __syncthreads();

        // matvec: 8 rows x 2 batches per thread, f32x2 packed
        unsigned long long acc[16];
        #pragma unroll
        for (int j = 0; j < 16; j++) acc[j] = 0ull;
        #pragma unroll
        for (int i = 0; i < 4; i++) {
            const int kb = 4 * lane + 128 * i;
            #pragma unroll
            for (int bb = 0; bb < 2; bb++) {
                ulonglong2 hv = *(const ulonglong2*)&hs[bb * 512 + kb];
                #pragma unroll
                for (int r = 0; r < 8; r++) {
                    fma2(acc[2 * r + bb], wq[r][2 * i],     hv.x);
                    fma2(acc[2 * r + bb], wq[r][2 * i + 1], hv.y);
                }
            }
        }

        float v[16];
        #pragma unroll
        for (int j = 0; j < 16; j++) v[j] = unpk_sum(acc[j]);

        // folded butterfly: bits 16,8,4,2 fold 16 values -> 1, bit 1 finishes k-reduce
        float t16[16];
        #pragma unroll
        for (int j = 0; j < 16; j++) t16[j] = __shfl_xor_sync(0xffffffffu, v[j], 16);
        const int s16 = (lane & 16) ? 8 : 0;
        float w8[8];
        #pragma unroll
        for (int j = 0; j < 8; j++) w8[j] = v[s16 + j] + t16[s16 + j];
        float t8[8];
        #pragma unroll
        for (int j = 0; j < 8; j++) t8[j] = __shfl_xor_sync(0xffffffffu, w8[j], 8);
        const int s8 = (lane & 8) ? 4 : 0;
        float w4[4];
        #pragma unroll
        for (int j = 0; j < 4; j++) w4[j] = w8[s8 + j] + t8[s8 + j];
        float t4[4];
        #pragma unroll
        for (int j = 0; j < 4; j++) t4[j] = __shfl_xor_sync(0xffffffffu, w4[j], 4);
        const int s4 = (lane & 4) ? 2 : 0;
        float w2[2];
        #pragma unroll
        for (int j = 0; j < 2; j++) w2[j] = w4[s4 + j] + t4[s4 + j];
        float t2a = __shfl_xor_sync(0xffffffffu, w2[0], 2);
        float t2b = __shfl_xor_sync(0xffffffffu, w2[1], 2);
        float w1 = (lane & 2) ? (w2[1] + t2b) : (w2[0] + t2a);
        float z = w1 + __shfl_xor_sync(0xffffffffu, w1, 1);

        // even lanes hold z for idx = 8*b4 + 4*b3 + 2*b2 + 1*b1; r = idx>>1, bb = idx&1
        const int idx = ((lane >> 4) & 1) * 8 + ((lane >> 3) & 1) * 4 +
                        ((lane >> 2) & 1) * 2 + ((lane >> 1) & 1);
        if (!(lane & 1)) {
            const int r = idx >> 1, bb = idx & 1;
            gsum[r & 3][2 * w + (r >> 2)][bb] = z;
        }
        __syncthreads();

        // gate warp (warp 0): 32 lanes = 16 j x 2 batches
        if (w == 0) {
            float gi = gsum[0][gjl][gbb] + xq0;
            float gf = gsum[1][gjl][gbb] + xq1;
            float gg = gsum[2][gjl][gbb] + xq2;
            float go = gsum[3][gjl][gbb] + xq3;
            float si = sigf(gi);
            float sf = sigf(gf);
            float so = sigf(go);
            float tg = tanhfast(gg);
            c_st = sf * c_st + si * tg;
            float hN = so * tanhfast(c_st);
            g_h[((size_t)(gB << 10) + t) * 512 + j0 + gjl] = hN;
            __syncwarp();
            if (lane == 0) red_rel_add(&ctr[t], 1u);
        }
    }
}

// ---------- bf16x3 tensor-core GEMM via mma.sync ----------
// C[M,N] = A[M,K] @ B[N,K]^T (+bias) (ReLU) (ACC) (rowmask). CTA 128x128, K-chunks of 32.
template<bool RELU, bool ACC, bool MASK>
__global__ __launch_bounds__(256, 1) void mma_gemm(
    const float* __restrict__ A, int lda, long long sA,
    const float* __restrict__ B, int ldb, long long sB,
    float* __restrict__ C, int ldc, long long sC,
    int K, const float* __restrict__ bias, const int* __restrict__ rowmask)
{
    __shared__ __align__(16) __nv_bfloat16 Ah[128][40], Al[128][40];
    __shared__ __align__(16) __nv_bfloat16 Bh[128][40], Bl[128][40];

    const int tid = threadIdx.x, wid = tid >> 5, lane = tid & 31;
    const int m0 = blockIdx.y * 128, n0 = blockIdx.x * 128;
    const int wm = wid & 3, wn = wid >> 2;
    A += (long long)blockIdx.z * sA;
    B += (long long)blockIdx.z * sB;
    C += (long long)blockIdx.z * sC;

    const int srow = tid >> 1;
    const int kseg = (tid & 1) * 16;
    const float* Ap = A + (size_t)(m0 + srow) * lda + kseg;
    const float* Bp = B + (size_t)(n0 + srow) * ldb + kseg;

    float c[2][8][4];
    #pragma unroll
    for (int i = 0; i < 2; i++)
        #pragma unroll
        for (int j = 0; j < 8; j++)
            #pragma unroll
            for (int q = 0; q < 4; q++) c[i][j][q] = 0.f;

    const int lr = lane & 15, lc = (lane >> 4) << 3;

    const int nkt = K >> 5;
    float4 pa[4], pb[4];
    #pragma unroll
    for (int i = 0; i < 4; i++) {
        pa[i] = *(const float4*)(Ap + i * 4);
        pb[i] = *(const float4*)(Bp + i * 4);
    }

    for (int kt = 0; kt < nkt; ++kt) {
        #pragma unroll
        for (int i = 0; i < 4; i++) {
            float4 a = pa[i], b = pb[i];
            int kk = kseg + 4 * i;
            __nv_bfloat162 h01 = __floats2bfloat162_rn(a.x, a.y);
            __nv_bfloat162 h23 = __floats2bfloat162_rn(a.z, a.w);
            *(__nv_bfloat162*)&Ah[srow][kk]     = h01;
            *(__nv_bfloat162*)&Ah[srow][kk + 2] = h23;
            *(__nv_bfloat162*)&Al[srow][kk]     = __floats2bfloat162_rn(
                a.x - __bfloat162float(h01.x), a.y - __bfloat162float(h01.y));
            *(__nv_bfloat162*)&Al[srow][kk + 2] = __floats2bfloat162_rn(
                a.z - __bfloat162float(h23.x), a.w - __bfloat162float(h23.y));
            __nv_bfloat162 g01 = __floats2bfloat162_rn(b.x, b.y);
            __nv_bfloat162 g23 = __floats2bfloat162_rn(b.z, b.w);
            *(__nv_bfloat162*)&Bh[srow][kk]     = g01;
            *(__nv_bfloat162*)&Bh[srow][kk + 2] = g23;
            *(__nv_bfloat162*)&Bl[srow][kk]     = __floats2bfloat162_rn(
                b.x - __bfloat162float(g01.x), b.y - __bfloat162float(g01.y));
            *(__nv_bfloat162*)&Bl[srow][kk + 2] = __floats2bfloat162_rn(
                b.z - __bfloat162float(g23.x), b.w - __bfloat162float(g23.y));
        }
        __syncthreads();

        if (kt + 1 < nkt) {
            const int ko = (kt + 1) << 5;
            #pragma unroll
            for (int i = 0; i < 4; i++) {
                pa[i] = *(const float4*)(Ap + ko + i * 4);
                pb[i] = *(const float4*)(Bp + ko + i * 4);
            }
        }

        #pragma unroll
        for (int k16 = 0; k16 < 2; ++k16) {
            const int k0 = k16 * 16 + lc;
            unsigned ah[2][4], al[2][4], bh[8][2], bl[8][2];
            #pragma unroll
            for (int mf = 0; mf < 2; mf++) {
                ldsm4(ah[mf], smem_u32(&Ah[wm * 32 + mf * 16 + lr][k0]));
                ldsm4(al[mf], smem_u32(&Al[wm * 32 + mf * 16 + lr][k0]));
            }
            #pragma unroll
            for (int ng = 0; ng < 4; ng++) {
                unsigned th[4], tl[4];
                ldsm4(th, smem_u32(&Bh[wn * 64 + ng * 16 + lr][k0]));
                ldsm4(tl, smem_u32(&Bl[wn * 64 + ng * 16 + lr][k0]));
                bh[2 * ng][0] = th[0]; bh[2 * ng][1] = th[2];
                bh[2 * ng + 1][0] = th[1]; bh[2 * ng + 1][1] = th[3];
                bl[2 * ng][0] = tl[0]; bl[2 * ng][1] = tl[2];
                bl[2 * ng + 1][0] = tl[1]; bl[2 * ng + 1][1] = tl[3];
            }
            #pragma unroll
            for (int mf = 0; mf < 2; mf++)
                #pragma unroll
                for (int nf = 0; nf < 8; nf++) {
                    mma16816(c[mf][nf], ah[mf], bh[nf]);
                    mma16816(c[mf][nf], ah[mf], bl[nf]);
                    mma16816(c[mf][nf], al[mf], bh[nf]);
                }
        }
        __syncthreads();
    }

    #pragma unroll
    for (int mf = 0; mf < 2; mf++) {
        const int row0 = m0 + wm * 32 + mf * 16 + (lane >> 2);
        const int row1 = row0 + 8;
        float keep0 = 1.f, keep1 = 1.f;
        if (MASK) {
            keep0 = rowmask[row0] ? 1.f : 0.f;
            keep1 = rowmask[row1] ? 1.f : 0.f;
        }
        #pragma unroll
        for (int nf = 0; nf < 8; nf++) {
            const int col = n0 + wn * 64 + nf * 8 + 2 * (lane & 3);
            float b0 = 0.f, b1 = 0.f;
            if (bias) { b0 = bias[col]; b1 = bias[col + 1]; }
            float o00 = c[mf][nf][0] + b0, o01 = c[mf][nf][1] + b1;
            float o10 = c[mf][nf][2] + b0, o11 = c[mf][nf][3] + b1;
            if (RELU) {
                o00 = fmaxf(o00, 0.f); o01 = fmaxf(o01, 0.f);
                o10 = fmaxf(o10, 0.f); o11 = fmaxf(o11, 0.f);
            }
            o00 *= keep0; o01 *= keep0; o10 *= keep1; o11 *= keep1;
            float* p0 = C + (size_t)row0 * ldc + col;
            float* p1 = C + (size_t)row1 * ldc + col;
            if (ACC) {
                float2 u0 = *(float2*)p0, u1 = *(float2*)p1;
                o00 += u0.x; o01 += u0.y; o10 += u1.x; o11 += u1.y;
            }
            *(float2*)p0 = make_float2(o00, o01);
            *(float2*)p1 = make_float2(o10, o11);
        }
    }
}

// ---------- transpose h[b][1024][512] -> hT[b][512][1024] ----------
__global__ __launch_bounds__(256) void transpose_kernel(
    const float* __restrict__ src, float* __restrict__ dst)
{
    __shared__ float tile[32][33];
    const int b = blockIdx.z;
    const int i0 = blockIdx.y * 32, j0 = blockIdx.x * 32;
    const int tx = threadIdx.x & 31, ty = threadIdx.x >> 5;
    #pragma unroll
    for (int rr = 0; rr < 32; rr += 8)
        tile[ty + rr][tx] = src[(size_t)b * 524288 + (size_t)(i0 + ty + rr) * 512 + j0 + tx];
    __syncthreads();
    #pragma unroll
    for (int rr = 0; rr < 32; rr += 8)
        dst[(size_t)b * 524288 + (size_t)(j0 + ty + rr) * 1024 + i0 + tx] = tile[tx][ty + rr];
}

// ---------- masked softmax per row (in place) + has-neighbor flag ----------
__global__ __launch_bounds__(256) void softmax_kernel(
    float* __restrict__ S, const int* __restrict__ adj, int* __restrict__ hasnb)
{
    __shared__ float sred[32];
    const int r = blockIdx.x;
    const int i = r & 1023;
    const int tid = threadIdx.x;
    float* Sr = S + (size_t)r * 1024;
    const int* Ar = adj + (size_t)r * 1024;

    float v[4]; int ok[4];
    float mx = -3.0e38f;
    #pragma unroll
    for (int q = 0; q < 4; q++) {
        int j = tid + 256 * q;
        ok[q] = (Ar[j] > 0) && (j != i);
        v[q] = Sr[j];
        if (ok[q]) mx = fmaxf(mx, v[q]);
    }
    #pragma unroll
    for (int off = 16; off > 0; off >>= 1)
        mx = fmaxf(mx, __shfl_xor_sync(0xffffffffu, mx, off));
    if ((tid & 31) == 0) sred[tid >> 5] = mx;
    __syncthreads();
    if (tid < 32) {
        float m2 = (tid < 8) ? sred[tid] : -3.0e38f;
        #pragma unroll
        for (int off = 4; off > 0; off >>= 1)
            m2 = fmaxf(m2, __shfl_xor_sync(0xffffffffu, m2, off));
        if (tid == 0) sred[0] = m2;
    }
    __syncthreads();
    const float rowmax = sred[0];
    const bool any = rowmax > -1.0e37f;

    float e[4];
    float s = 0.f;
    #pragma unroll
    for (int q = 0; q < 4; q++) {
        e[q] = ok[q] ? __expf(v[q] - rowmax) : 0.f;
        s += e[q];
    }
    #pragma unroll
    for (int off = 16; off > 0; off >>= 1)
        s += __shfl_xor_sync(0xffffffffu, s, off);
    __syncthreads();
    if ((tid & 31) == 0) sred[tid >> 5] = s;
    __syncthreads();
    if (tid < 32) {
        float s2 = (tid < 8) ? sred[tid] : 0.f;
        #pragma unroll
        for (int off = 4; off > 0; off >>= 1)
            s2 += __shfl_xor_sync(0xffffffffu, s2, off);
        if (tid == 0) sred[0] = s2;
    }
    __syncthreads();
    const float inv = any ? (1.f / sred[0]) : 0.f;
    #pragma unroll
    for (int q = 0; q < 4; q++)
        Sr[tid + 256 * q] = e[q] * inv;
    if (tid == 0) hasnb[r] = any ? 1 : 0;
}

extern "C" void kernel_launch(void* const* d_in, const int* in_sizes, int n_in,
                              void* d_out, int out_size)
{
    const float* feats  = (const float*)d_in[0];
    const int*   adj    = (const int*)  d_in[1];
    const float* W_ih   = (const float*)d_in[2];
    const float* W_hh   = (const float*)d_in[3];
    const float* b_ih   = (const float*)d_in[4];
    const float* b_hh   = (const float*)d_in[5];
    const float* gx_W1  = (const float*)d_in[6];
    const float* gx_b1  = (const float*)d_in[7];
    const float* gx_W2  = (const float*)d_in[8];
    const float* gx_b2  = (const float*)d_in[9];
    const float* gz_W1  = (const float*)d_in[10];
    const float* gz_b1  = (const float*)d_in[11];
    const float* gz_W2  = (const float*)d_in[12];
    const float* gz_b2  = (const float*)d_in[13];
    const float* gv_W1  = (const float*)d_in[14];
    const float* gv_b1  = (const float*)d_in[15];
    const float* gv_W2  = (const float*)d_in[16];
    const float* gv_b2  = (const float*)d_in[17];
    const float* gn_W1  = (const float*)d_in[18];
    const float* gn_b1  = (const float*)d_in[19];
    const float* gn_W2  = (const float*)d_in[20];
    const float* gn_b2  = (const float*)d_in[21];
    const float* out_W  = (const float*)d_in[22];
    const float* out_b  = (const float*)d_in[23];
    float* out = (float*)d_out;

    float *xproj, *h, *hT, *t1, *t2, *t3, *ax, *av, *scores, *sagg, *agg, *bsum;
    int* hasnb;
    cudaGetSymbolAddress((void**)&xproj,  g_xproj);
    cudaGetSymbolAddress((void**)&h,      g_h);
    cudaGetSymbolAddress((void**)&hT,     g_hT);
    cudaGetSymbolAddress((void**)&t1,     g_t1);
    cudaGetSymbolAddress((void**)&t2,     g_t2);
    cudaGetSymbolAddress((void**)&t3,     g_t3);
    cudaGetSymbolAddress((void**)&ax,     g_ax);
    cudaGetSymbolAddress((void**)&av,     g_av);
    cudaGetSymbolAddress((void**)&scores, g_scores);
    cudaGetSymbolAddress((void**)&sagg,   g_sagg);
    cudaGetSymbolAddress((void**)&agg,    g_agg);
    cudaGetSymbolAddress((void**)&bsum,   g_bsum);
    cudaGetSymbolAddress((void**)&hasnb,  g_hasnb);

    reset_kernel<<<1, 1024>>>(b_ih, b_hh);

    // x_proj = feats @ W_ih^T + (b_ih + b_hh) : [8192,2048], K=256
    mma_gemm<false, false, false><<<dim3(16, 64, 1), 256>>>(
        feats, 256, 0, W_ih, 256, 0, xproj, 2048, 0, 256, bsum, nullptr);

    lstm_kernel<<<128, 256>>>(W_hh);

    // ax = MLP_gx(h), av = MLP_gv(h)
    mma_gemm<true , false, false><<<dim3(2, 64, 1), 256>>>(
        h, 512, 0, gx_W1, 512, 0, t1, 256, 0, 512, gx_b1, nullptr);
    mma_gemm<true , false, false><<<dim3(2, 64, 1), 256>>>(
        h, 512, 0, gv_W1, 512, 0, t3, 256, 0, 512, gv_b1, nullptr);
    mma_gemm<false, false, false><<<dim3(2, 64, 1), 256>>>(
        t1, 256, 0, gx_W2, 256, 0, ax, 256, 0, 256, gx_b2, nullptr);
    mma_gemm<false, false, false><<<dim3(2, 64, 1), 256>>>(
        t3, 256, 0, gv_W2, 256, 0, av, 256, 0, 256, gv_b2, nullptr);

    // scores[b] = ax[b] @ av[b]^T
    mma_gemm<false, false, false><<<dim3(8, 8, 8), 256>>>(
        ax, 256, 262144LL, av, 256, 262144LL, scores, 1024, 1048576LL, 256, nullptr, nullptr);

    softmax_kernel<<<8192, 256>>>(scores, adj, hasnb);

    // hT = transpose(h); sagg[b] = w[b] @ h[b]  (NT via hT)
    transpose_kernel<<<dim3(16, 32, 8), 256>>>(h, hT);
    mma_gemm<false, false, false><<<dim3(4, 8, 8), 256>>>(
        scores, 1024, 1048576LL, hT, 1024, 524288LL, sagg, 512, 524288LL, 1024, nullptr, nullptr);

    // agg = MLP_gn(MLP_gz(sagg)), isolated nodes zeroed at the last layer
    mma_gemm<true , false, false><<<dim3(2, 64, 1), 256>>>(
        sagg, 512, 0, gz_W1, 512, 0, t1, 256, 0, 512, gz_b1, nullptr);
    mma_gemm<false, false, false><<<dim3(2, 64, 1), 256>>>(
        t1, 256, 0, gz_W2, 256, 0, t2, 256, 0, 256, gz_b2, nullptr);
    mma_gemm<true , false, false><<<dim3(2, 64, 1), 256>>>(
        t2, 256, 0, gn_W1, 256, 0, t1, 256, 0, 256, gn_b1, nullptr);
    mma_gemm<false, false, true ><<<dim3(2, 64, 1), 256>>>(
        t1, 256, 0, gn_W2, 256, 0, agg, 256, 0, 256, gn_b2, hasnb);

    // out = h @ out_W[:, :512]^T + out_b ; out += agg @ out_W[:, 512:]^T
    mma_gemm<false, false, false><<<dim3(2, 64, 1), 256>>>(
        h, 512, 0, out_W, 768, 0, out, 256, 0, 512, out_b, nullptr);
    mma_gemm<false, true , false><<<dim3(2, 64, 1), 256>>>(
        agg, 256, 0, out_W + 512, 768, 0, out, 256, 0, 256, nullptr, nullptr);
}

// round 14
// speedup vs baseline: 1.5347x; 1.2850x over previous
#include <cuda_runtime.h>
#include <cuda_bf16.h>

// B=8, N=1024, D=256, H=512, M=256, O=256, 4H=2048

__device__ float g_xproj[8 * 1024 * 2048];
__device__ float g_h    [8 * 1024 * 512];
__device__ float g_hT   [8 * 512 * 1024];
__device__ float g_t1   [8 * 1024 * 256];
__device__ float g_t2   [8 * 1024 * 256];
__device__ float g_t3   [8 * 1024 * 256];
__device__ float g_ax   [8 * 1024 * 256];
__device__ float g_av   [8 * 1024 * 256];
__device__ float g_scores[8 * 1024 * 1024];
__device__ float g_sagg [8 * 1024 * 512];
__device__ float g_agg  [8 * 1024 * 256];
__device__ float g_bsum [2048];
__device__ int   g_hasnb[8 * 1024];
__device__ unsigned long long g_stage[2][8][512];   // (f32 h, u32 tag) double-buffered

// ---------------- helpers ----------------
__device__ __forceinline__ unsigned long long pk2(float lo, float hi) {
    unsigned long long r;
    asm("mov.b64 %0, {%1, %2};" : "=l"(r) : "f"(lo), "f"(hi));
    return r;
}
__device__ __forceinline__ void fma2(unsigned long long& d, unsigned long long a, unsigned long long b) {
    asm("fma.rn.f32x2 %0, %1, %2, %0;" : "+l"(d) : "l"(a), "l"(b));
}
__device__ __forceinline__ float unpk_sum(unsigned long long v) {
    float x, y;
    asm("mov.b64 {%0, %1}, %2;" : "=f"(x), "=f"(y) : "l"(v));
    return x + y;
}
__device__ __forceinline__ unsigned long long pk_ft(float h, unsigned tag) {
    unsigned long long r;
    asm("mov.b64 %0, {%1, %2};" : "=l"(r) : "f"(h), "r"(tag));
    return r;
}
__device__ __forceinline__ void unpk_ft(unsigned long long v, float& h, unsigned& tag) {
    asm("mov.b64 {%0, %1}, %2;" : "=f"(h), "=r"(tag) : "l"(v));
}
__device__ __forceinline__ void st_rlx_u64(unsigned long long* p, unsigned long long v) {
    asm volatile("st.relaxed.gpu.global.u64 [%0], %1;" :: "l"(p), "l"(v) : "memory");
}
__device__ __forceinline__ ulonglong2 ld_rlx_v2(const unsigned long long* p) {
    ulonglong2 r;
    asm volatile("ld.relaxed.gpu.global.v2.u64 {%0,%1}, [%2];"
                 : "=l"(r.x), "=l"(r.y) : "l"(p) : "memory");
    return r;
}
__device__ __forceinline__ float sigf(float x) {
    return __fdividef(1.f, 1.f + __expf(-x));
}
__device__ __forceinline__ float tanhfast(float x) {
    return __fdividef(2.f, 1.f + __expf(-2.f * x)) - 1.f;
}
__device__ __forceinline__ unsigned smem_u32(const void* p) {
    unsigned a;
    asm("{ .reg .u64 t; cvta.to.shared.u64 t, %1; cvt.u32.u64 %0, t; }" : "=r"(a) : "l"(p));
    return a;
}
__device__ __forceinline__ void ldsm4(unsigned* r, unsigned addr) {
    asm volatile("ldmatrix.sync.aligned.m8n8.x4.shared.b16 {%0,%1,%2,%3}, [%4];"
                 : "=r"(r[0]), "=r"(r[1]), "=r"(r[2]), "=r"(r[3]) : "r"(addr));
}
__device__ __forceinline__ void mma16816(float* c, const unsigned* a, const unsigned* b) {
    asm volatile(
        "mma.sync.aligned.m16n8k16.row.col.f32.bf16.bf16.f32 "
        "{%0,%1,%2,%3}, {%4,%5,%6,%7}, {%8,%9}, {%0,%1,%2,%3};"
        : "+f"(c[0]), "+f"(c[1]), "+f"(c[2]), "+f"(c[3])
        : "r"(a[0]), "r"(a[1]), "r"(a[2]), "r"(a[3]), "r"(b[0]), "r"(b[1]));
}

__global__ void reset_kernel(const float* __restrict__ b_ih, const float* __restrict__ b_hh) {
    int t = threadIdx.x;
    g_bsum[t] = b_ih[t] + b_hh[t];
    g_bsum[t + 1024] = b_ih[t + 1024] + b_hh[t + 1024];
}

// ---------- persistent LSTM: 4 independent batch-pair chains x 32 CTAs ----------
// Sync is fused into data: (h, tag) u64 words in g_stage, double-buffered.
// group = blockIdx>>5 owns batches {2g, 2g+1}. CTA-in-group cg owns j in [16cg, 16cg+16),
// all 4 gates (64 gate rows). Warp w owns jl in {2w, 2w+1} x 4 gates.
__global__ __launch_bounds__(256, 1) void lstm_kernel(const float* __restrict__ Whh)
{
    __shared__ __align__(16) float hs[2 * 512];
    __shared__ float gsum[4][16][2];

    const int tid   = threadIdx.x;
    const int w     = tid >> 5;
    const int lane  = tid & 31;
    const int group = blockIdx.x >> 5;
    const int cg    = blockIdx.x & 31;
    const int j0    = cg * 16;
    const int b0    = group * 2;

    // weights: 8 rows (gate = r&3, jl = 2w + (r>>2)) x 16 k (k = 4*lane + 128*i)
    unsigned long long wq[8][8];
    #pragma unroll
    for (int r = 0; r < 8; r++) {
        const int gt = r & 3;
        const int jl = 2 * w + (r >> 2);
        const size_t grow = (size_t)(gt * 512 + j0 + jl) * 512;
        #pragma unroll
        for (int i = 0; i < 4; i++) {
            float4 a = *(const float4*)&Whh[grow + 4 * lane + 128 * i];
            wq[r][2 * i]     = pk2(a.x, a.y);
            wq[r][2 * i + 1] = pk2(a.z, a.w);
        }
    }

    float c_st = 0.f;
    const int gjl = lane >> 1;    // gate-warp local j
    const int gbb = lane & 1;     // gate-warp batch-in-pair
    const int gB  = b0 + gbb;     // gate-warp global batch

    // consumer staging coords: thread -> 4 consecutive j of one batch
    const int cbb = tid >> 7;            // batch-in-pair
    const int cjj = (tid & 127) * 4;     // j base

    for (int t = 0; t < 1024; ++t) {
        // prefetch x-projection gate inputs (independent of h[t-1])
        float xq0 = 0.f, xq1 = 0.f, xq2 = 0.f, xq3 = 0.f;
        if (w == 0) {
            size_t base = ((size_t)(gB << 10) + t) * 2048 + j0 + gjl;
            xq0 = g_xproj[base];
            xq1 = g_xproj[base + 512];
            xq2 = g_xproj[base + 1024];
            xq3 = g_xproj[base + 1536];
        }

        // acquire h[t-1] by polling tagged staging words (sync fused into data)
        if (t == 0) {
            *(float4*)&hs[4 * tid] = make_float4(0.f, 0.f, 0.f, 0.f);
        } else {
            const unsigned long long* sp = &g_stage[(t - 1) & 1][b0 + cbb][cjj];
            const unsigned e = (unsigned)t;
            ulonglong2 a, b;
            for (;;) {
                a = ld_rlx_v2(sp);
                b = ld_rlx_v2(sp + 2);
                float h0, h1, h2, h3;
                unsigned t0, t1_, t2_, t3_;
                unpk_ft(a.x, h0, t0); unpk_ft(a.y, h1, t1_);
                unpk_ft(b.x, h2, t2_); unpk_ft(b.y, h3, t3_);
                if ((t0 == e) & (t1_ == e) & (t2_ == e) & (t3_ == e)) {
                    *(float4*)&hs[cbb * 512 + cjj] = make_float4(h0, h1, h2, h3);
                    break;
                }
            }
        }
        __syncthreads();

        // matvec: 8 rows x 2 batches per thread, f32x2 packed
        unsigned long long acc[16];
        #pragma unroll
        for (int j = 0; j < 16; j++) acc[j] = 0ull;
        #pragma unroll
        for (int i = 0; i < 4; i++) {
            const int kb = 4 * lane + 128 * i;
            #pragma unroll
            for (int bb = 0; bb < 2; bb++) {
                ulonglong2 hv = *(const ulonglong2*)&hs[bb * 512 + kb];
                #pragma unroll
                for (int r = 0; r < 8; r++) {
                    fma2(acc[2 * r + bb], wq[r][2 * i],     hv.x);
                    fma2(acc[2 * r + bb], wq[r][2 * i + 1], hv.y);
                }
            }
        }

        float v[16];
        #pragma unroll
        for (int j = 0; j < 16; j++) v[j] = unpk_sum(acc[j]);

        // folded butterfly: bits 16,8,4,2 fold 16 values -> 1, bit 1 finishes k-reduce
        float t16[16];
        #pragma unroll
        for (int j = 0; j < 16; j++) t16[j] = __shfl_xor_sync(0xffffffffu, v[j], 16);
        const int s16 = (lane & 16) ? 8 : 0;
        float w8[8];
        #pragma unroll
        for (int j = 0; j < 8; j++) w8[j] = v[s16 + j] + t16[s16 + j];
        float t8[8];
        #pragma unroll
        for (int j = 0; j < 8; j++) t8[j] = __shfl_xor_sync(0xffffffffu, w8[j], 8);
        const int s8 = (lane & 8) ? 4 : 0;
        float w4[4];
        #pragma unroll
        for (int j = 0; j < 4; j++) w4[j] = w8[s8 + j] + t8[s8 + j];
        float t4[4];
        #pragma unroll
        for (int j = 0; j < 4; j++) t4[j] = __shfl_xor_sync(0xffffffffu, w4[j], 4);
        const int s4 = (lane & 4) ? 2 : 0;
        float w2[2];
        #pragma unroll
        for (int j = 0; j < 2; j++) w2[j] = w4[s4 + j] + t4[s4 + j];
        float t2a = __shfl_xor_sync(0xffffffffu, w2[0], 2);
        float t2b = __shfl_xor_sync(0xffffffffu, w2[1], 2);
        float w1 = (lane & 2) ? (w2[1] + t2b) : (w2[0] + t2a);
        float z = w1 + __shfl_xor_sync(0xffffffffu, w1, 1);

        // even lanes hold z for idx = 8*b4 + 4*b3 + 2*b2 + 1*b1; r = idx>>1, bb = idx&1
        const int idx = ((lane >> 4) & 1) * 8 + ((lane >> 3) & 1) * 4 +
                        ((lane >> 2) & 1) * 2 + ((lane >> 1) & 1);
        if (!(lane & 1)) {
            const int r = idx >> 1, bb = idx & 1;
            gsum[r & 3][2 * w + (r >> 2)][bb] = z;
        }
        __syncthreads();

        // gate warp (warp 0): 32 lanes = 16 j x 2 batches; publish tagged h
        if (w == 0) {
            float gi = gsum[0][gjl][gbb] + xq0;
            float gf = gsum[1][gjl][gbb] + xq1;
            float gg = gsum[2][gjl][gbb] + xq2;
            float go = gsum[3][gjl][gbb] + xq3;
            float si = sigf(gi);
            float sf = sigf(gf);
            float so = sigf(go);
            float tg = tanhfast(gg);
            c_st = sf * c_st + si * tg;
            float hN = so * tanhfast(c_st);
            g_h[((size_t)(gB << 10) + t) * 512 + j0 + gjl] = hN;
            st_rlx_u64(&g_stage[t & 1][gB][j0 + gjl], pk_ft(hN, (unsigned)(t + 1)));
        }
    }
}

// ---------- bf16x3 tensor-core GEMM via mma.sync ----------
// C[M,N] = A[M,K] @ B[N,K]^T (+bias) (ReLU) (ACC) (rowmask). CTA 128x128, K-chunks of 32.
template<bool RELU, bool ACC, bool MASK>
__global__ __launch_bounds__(256, 1) void mma_gemm(
    const float* __restrict__ A, int lda, long long sA,
    const float* __restrict__ B, int ldb, long long sB,
    float* __restrict__ C, int ldc, long long sC,
    int K, const float* __restrict__ bias, const int* __restrict__ rowmask)
{
    __shared__ __align__(16) __nv_bfloat16 Ah[128][40], Al[128][40];
    __shared__ __align__(16) __nv_bfloat16 Bh[128][40], Bl[128][40];

    const int tid = threadIdx.x, wid = tid >> 5, lane = tid & 31;
    const int m0 = blockIdx.y * 128, n0 = blockIdx.x * 128;
    const int wm = wid & 3, wn = wid >> 2;
    A += (long long)blockIdx.z * sA;
    B += (long long)blockIdx.z * sB;
    C += (long long)blockIdx.z * sC;

    const int srow = tid >> 1;
    const int kseg = (tid & 1) * 16;
    const float* Ap = A + (size_t)(m0 + srow) * lda + kseg;
    const float* Bp = B + (size_t)(n0 + srow) * ldb + kseg;

    float c[2][8][4];
    #pragma unroll
    for (int i = 0; i < 2; i++)
        #pragma unroll
        for (int j = 0; j < 8; j++)
            #pragma unroll
            for (int q = 0; q < 4; q++) c[i][j][q] = 0.f;

    const int lr = lane & 15, lc = (lane >> 4) << 3;

    const int nkt = K >> 5;
    float4 pa[4], pb[4];
    #pragma unroll
    for (int i = 0; i < 4; i++) {
        pa[i] = *(const float4*)(Ap + i * 4);
        pb[i] = *(const float4*)(Bp + i * 4);
    }

    for (int kt = 0; kt < nkt; ++kt) {
        #pragma unroll
        for (int i = 0; i < 4; i++) {
            float4 a = pa[i], b = pb[i];
            int kk = kseg + 4 * i;
            __nv_bfloat162 h01 = __floats2bfloat162_rn(a.x, a.y);
            __nv_bfloat162 h23 = __floats2bfloat162_rn(a.z, a.w);
            *(__nv_bfloat162*)&Ah[srow][kk]     = h01;
            *(__nv_bfloat162*)&Ah[srow][kk + 2] = h23;
            *(__nv_bfloat162*)&Al[srow][kk]     = __floats2bfloat162_rn(
                a.x - __bfloat162float(h01.x), a.y - __bfloat162float(h01.y));
            *(__nv_bfloat162*)&Al[srow][kk + 2] = __floats2bfloat162_rn(
                a.z - __bfloat162float(h23.x), a.w - __bfloat162float(h23.y));
            __nv_bfloat162 g01 = __floats2bfloat162_rn(b.x, b.y);
            __nv_bfloat162 g23 = __floats2bfloat162_rn(b.z, b.w);
            *(__nv_bfloat162*)&Bh[srow][kk]     = g01;
            *(__nv_bfloat162*)&Bh[srow][kk + 2] = g23;
            *(__nv_bfloat162*)&Bl[srow][kk]     = __floats2bfloat162_rn(
                b.x - __bfloat162float(g01.x), b.y - __bfloat162float(g01.y));
            *(__nv_bfloat162*)&Bl[srow][kk + 2] = __floats2bfloat162_rn(
                b.z - __bfloat162float(g23.x), b.w - __bfloat162float(g23.y));
        }
        __syncthreads();

        if (kt + 1 < nkt) {
            const int ko = (kt + 1) << 5;
            #pragma unroll
            for (int i = 0; i < 4; i++) {
                pa[i] = *(const float4*)(Ap + ko + i * 4);
                pb[i] = *(const float4*)(Bp + ko + i * 4);
            }
        }

        #pragma unroll
        for (int k16 = 0; k16 < 2; ++k16) {
            const int k0 = k16 * 16 + lc;
            unsigned ah[2][4], al[2][4], bh[8][2], bl[8][2];
            #pragma unroll
            for (int mf = 0; mf < 2; mf++) {
                ldsm4(ah[mf], smem_u32(&Ah[wm * 32 + mf * 16 + lr][k0]));
                ldsm4(al[mf], smem_u32(&Al[wm * 32 + mf * 16 + lr][k0]));
            }
            #pragma unroll
            for (int ng = 0; ng < 4; ng++) {
                unsigned th[4], tl[4];
                ldsm4(th, smem_u32(&Bh[wn * 64 + ng * 16 + lr][k0]));
                ldsm4(tl, smem_u32(&Bl[wn * 64 + ng * 16 + lr][k0]));
                bh[2 * ng][0] = th[0]; bh[2 * ng][1] = th[2];
                bh[2 * ng + 1][0] = th[1]; bh[2 * ng + 1][1] = th[3];
                bl[2 * ng][0] = tl[0]; bl[2 * ng][1] = tl[2];
                bl[2 * ng + 1][0] = tl[1]; bl[2 * ng + 1][1] = tl[3];
            }
            #pragma unroll
            for (int mf = 0; mf < 2; mf++)
                #pragma unroll
                for (int nf = 0; nf < 8; nf++) {
                    mma16816(c[mf][nf], ah[mf], bh[nf]);
                    mma16816(c[mf][nf], ah[mf], bl[nf]);
                    mma16816(c[mf][nf], al[mf], bh[nf]);
                }
        }
        __syncthreads();
    }

    #pragma unroll
    for (int mf = 0; mf < 2; mf++) {
        const int row0 = m0 + wm * 32 + mf * 16 + (lane >> 2);
        const int row1 = row0 + 8;
        float keep0 = 1.f, keep1 = 1.f;
        if (MASK) {
            keep0 = rowmask[row0] ? 1.f : 0.f;
            keep1 = rowmask[row1] ? 1.f : 0.f;
        }
        #pragma unroll
        for (int nf = 0; nf < 8; nf++) {
            const int col = n0 + wn * 64 + nf * 8 + 2 * (lane & 3);
            float b0 = 0.f, b1 = 0.f;
            if (bias) { b0 = bias[col]; b1 = bias[col + 1]; }
            float o00 = c[mf][nf][0] + b0, o01 = c[mf][nf][1] + b1;
            float o10 = c[mf][nf][2] + b0, o11 = c[mf][nf][3] + b1;
            if (RELU) {
                o00 = fmaxf(o00, 0.f); o01 = fmaxf(o01, 0.f);
                o10 = fmaxf(o10, 0.f); o11 = fmaxf(o11, 0.f);
            }
            o00 *= keep0; o01 *= keep0; o10 *= keep1; o11 *= keep1;
            float* p0 = C + (size_t)row0 * ldc + col;
            float* p1 = C + (size_t)row1 * ldc + col;
            if (ACC) {
                float2 u0 = *(float2*)p0, u1 = *(float2*)p1;
                o00 += u0.x; o01 += u0.y; o10 += u1.x; o11 += u1.y;
            }
            *(float2*)p0 = make_float2(o00, o01);
            *(float2*)p1 = make_float2(o10, o11);
        }
    }
}

// ---------- transpose h[b][1024][512] -> hT[b][512][1024] ----------
__global__ __launch_bounds__(256) void transpose_kernel(
    const float* __restrict__ src, float* __restrict__ dst)
{
    __shared__ float tile[32][33];
    const int b = blockIdx.z;
    const int i0 = blockIdx.y * 32, j0 = blockIdx.x * 32;
    const int tx = threadIdx.x & 31, ty = threadIdx.x >> 5;
    #pragma unroll
    for (int rr = 0; rr < 32; rr += 8)
        tile[ty + rr][tx] = src[(size_t)b * 524288 + (size_t)(i0 + ty + rr) * 512 + j0 + tx];
    __syncthreads();
    #pragma unroll
    for (int rr = 0; rr < 32; rr += 8)
        dst[(size_t)b * 524288 + (size_t)(j0 + ty + rr) * 1024 + i0 + tx] = tile[tx][ty + rr];
}

// ---------- masked softmax per row (in place) + has-neighbor flag ----------
__global__ __launch_bounds__(256) void softmax_kernel(
    float* __restrict__ S, const int* __restrict__ adj, int* __restrict__ hasnb)
{
    __shared__ float sred[32];
    const int r = blockIdx.x;
    const int i = r & 1023;
    const int tid = threadIdx.x;
    float* Sr = S + (size_t)r * 1024;
    const int* Ar = adj + (size_t)r * 1024;

    float v[4]; int ok[4];
    float mx = -3.0e38f;
    #pragma unroll
    for (int q = 0; q < 4; q++) {
        int j = tid + 256 * q;
        ok[q] = (Ar[j] > 0) && (j != i);
        v[q] = Sr[j];
        if (ok[q]) mx = fmaxf(mx, v[q]);
    }
    #pragma unroll
    for (int off = 16; off > 0; off >>= 1)
        mx = fmaxf(mx, __shfl_xor_sync(0xffffffffu, mx, off));
    if ((tid & 31) == 0) sred[tid >> 5] = mx;
    __syncthreads();
    if (tid < 32) {
        float m2 = (tid < 8) ? sred[tid] : -3.0e38f;
        #pragma unroll
        for (int off = 4; off > 0; off >>= 1)
            m2 = fmaxf(m2, __shfl_xor_sync(0xffffffffu, m2, off));
        if (tid == 0) sred[0] = m2;
    }
    __syncthreads();
    const float rowmax = sred[0];
    const bool any = rowmax > -1.0e37f;

    float e[4];
    float s = 0.f;
    #pragma unroll
    for (int q = 0; q < 4; q++) {
        e[q] = ok[q] ? __expf(v[q] - rowmax) : 0.f;
        s += e[q];
    }
    #pragma unroll
    for (int off = 16; off > 0; off >>= 1)
        s += __shfl_xor_sync(0xffffffffu, s, off);
    __syncthreads();
    if ((tid & 31) == 0) sred[tid >> 5] = s;
    __syncthreads();
    if (tid < 32) {
        float s2 = (tid < 8) ? sred[tid] : 0.f;
        #pragma unroll
        for (int off = 4; off > 0; off >>= 1)
            s2 += __shfl_xor_sync(0xffffffffu, s2, off);
        if (tid == 0) sred[0] = s2;
    }
    __syncthreads();
    const float inv = any ? (1.f / sred[0]) : 0.f;
    #pragma unroll
    for (int q = 0; q < 4; q++)
        Sr[tid + 256 * q] = e[q] * inv;
    if (tid == 0) hasnb[r] = any ? 1 : 0;
}

extern "C" void kernel_launch(void* const* d_in, const int* in_sizes, int n_in,
                              void* d_out, int out_size)
{
    const float* feats  = (const float*)d_in[0];
    const int*   adj    = (const int*)  d_in[1];
    const float* W_ih   = (const float*)d_in[2];
    const float* W_hh   = (const float*)d_in[3];
    const float* b_ih   = (const float*)d_in[4];
    const float* b_hh   = (const float*)d_in[5];
    const float* gx_W1  = (const float*)d_in[6];
    const float* gx_b1  = (const float*)d_in[7];
    const float* gx_W2  = (const float*)d_in[8];
    const float* gx_b2  = (const float*)d_in[9];
    const float* gz_W1  = (const float*)d_in[10];
    const float* gz_b1  = (const float*)d_in[11];
    const float* gz_W2  = (const float*)d_in[12];
    const float* gz_b2  = (const float*)d_in[13];
    const float* gv_W1  = (const float*)d_in[14];
    const float* gv_b1  = (const float*)d_in[15];
    const float* gv_W2  = (const float*)d_in[16];
    const float* gv_b2  = (const float*)d_in[17];
    const float* gn_W1  = (const float*)d_in[18];
    const float* gn_b1  = (const float*)d_in[19];
    const float* gn_W2  = (const float*)d_in[20];
    const float* gn_b2  = (const float*)d_in[21];
    const float* out_W  = (const float*)d_in[22];
    const float* out_b  = (const float*)d_in[23];
    float* out = (float*)d_out;

    float *xproj, *h, *hT, *t1, *t2, *t3, *ax, *av, *scores, *sagg, *agg, *bsum;
    int* hasnb;
    cudaGetSymbolAddress((void**)&xproj,  g_xproj);
    cudaGetSymbolAddress((void**)&h,      g_h);
    cudaGetSymbolAddress((void**)&hT,     g_hT);
    cudaGetSymbolAddress((void**)&t1,     g_t1);
    cudaGetSymbolAddress((void**)&t2,     g_t2);
    cudaGetSymbolAddress((void**)&t3,     g_t3);
    cudaGetSymbolAddress((void**)&ax,     g_ax);
    cudaGetSymbolAddress((void**)&av,     g_av);
    cudaGetSymbolAddress((void**)&scores, g_scores);
    cudaGetSymbolAddress((void**)&sagg,   g_sagg);
    cudaGetSymbolAddress((void**)&agg,    g_agg);
    cudaGetSymbolAddress((void**)&bsum,   g_bsum);
    cudaGetSymbolAddress((void**)&hasnb,  g_hasnb);

    reset_kernel<<<1, 1024>>>(b_ih, b_hh);

    // x_proj = feats @ W_ih^T + (b_ih + b_hh) : [8192,2048], K=256
    mma_gemm<false, false, false><<<dim3(16, 64, 1), 256>>>(
        feats, 256, 0, W_ih, 256, 0, xproj, 2048, 0, 256, bsum, nullptr);

    lstm_kernel<<<128, 256>>>(W_hh);

    // ax = MLP_gx(h), av = MLP_gv(h)
    mma_gemm<true , false, false><<<dim3(2, 64, 1), 256>>>(
        h, 512, 0, gx_W1, 512, 0, t1, 256, 0, 512, gx_b1, nullptr);
    mma_gemm<true , false, false><<<dim3(2, 64, 1), 256>>>(
        h, 512, 0, gv_W1, 512, 0, t3, 256, 0, 512, gv_b1, nullptr);
    mma_gemm<false, false, false><<<dim3(2, 64, 1), 256>>>(
        t1, 256, 0, gx_W2, 256, 0, ax, 256, 0, 256, gx_b2, nullptr);
    mma_gemm<false, false, false><<<dim3(2, 64, 1), 256>>>(
        t3, 256, 0, gv_W2, 256, 0, av, 256, 0, 256, gv_b2, nullptr);

    // scores[b] = ax[b] @ av[b]^T
    mma_gemm<false, false, false><<<dim3(8, 8, 8), 256>>>(
        ax, 256, 262144LL, av, 256, 262144LL, scores, 1024, 1048576LL, 256, nullptr, nullptr);

    softmax_kernel<<<8192, 256>>>(scores, adj, hasnb);

    // hT = transpose(h); sagg[b] = w[b] @ h[b]  (NT via hT)
    transpose_kernel<<<dim3(16, 32, 8), 256>>>(h, hT);
    mma_gemm<false, false, false><<<dim3(4, 8, 8), 256>>>(
        scores, 1024, 1048576LL, hT, 1024, 524288LL, sagg, 512, 524288LL, 1024, nullptr, nullptr);

    // agg = MLP_gn(MLP_gz(sagg)), isolated nodes zeroed at the last layer
    mma_gemm<true , false, false><<<dim3(2, 64, 1), 256>>>(
        sagg, 512, 0, gz_W1, 512, 0, t1, 256, 0, 512, gz_b1, nullptr);
    mma_gemm<false, false, false><<<dim3(2, 64, 1), 256>>>(
        t1, 256, 0, gz_W2, 256, 0, t2, 256, 0, 256, gz_b2, nullptr);
    mma_gemm<true , false, false><<<dim3(2, 64, 1), 256>>>(
        t2, 256, 0, gn_W1, 256, 0, t1, 256, 0, 256, gn_b1, nullptr);
    mma_gemm<false, false, true ><<<dim3(2, 64, 1), 256>>>(
        t1, 256, 0, gn_W2, 256, 0, agg, 256, 0, 256, gn_b2, hasnb);

    // out = h @ out_W[:, :512]^T + out_b ; out += agg @ out_W[:, 512:]^T
    mma_gemm<false, false, false><<<dim3(2, 64, 1), 256>>>(
        h, 512, 0, out_W, 768, 0, out, 256, 0, 512, out_b, nullptr);
    mma_gemm<false, true , false><<<dim3(2, 64, 1), 256>>>(
        agg, 256, 0, out_W + 512, 768, 0, out, 256, 0, 256, nullptr, nullptr);
}